// round 12
// baseline (speedup 1.0000x reference)
#include <cuda_runtime.h>
#include <cuda_bf16.h>
#include <math.h>
#include <stdint.h>

// Problem constants
#define BB    2
#define TT    1024
#define DD    1024
#define HH    16
#define DHH   64
#define NEXP  8
#define NTOK  2048          // B*T
#define DFF   4096
#define CAP   512           // NTOK*TOPK/NEXP

typedef __nv_bfloat16 bf16;

// ---------------- scratch (device globals: allocation-free) ----------------
__device__ __align__(128) bf16  g_hHi [NTOK * DD];
__device__ __align__(128) bf16  g_hLo [NTOK * DD];
__device__ __align__(128) bf16  g_qkvHi[NTOK * 3 * DD];   // rope applied, split
__device__ __align__(128) bf16  g_qkvLo[NTOK * 3 * DD];
__device__ __align__(128) bf16  g_aoHi[NTOK * DD];
__device__ __align__(128) bf16  g_aoLo[NTOK * DD];
__device__ __align__(128) float g_x2  [NTOK * DD];
__device__ __align__(128) float g_h2  [NTOK * DD];
__device__ __align__(128) bf16  g_h2Hi[NTOK * DD];
__device__ __align__(128) bf16  g_h2Lo[NTOK * DD];
__device__ __align__(128) float2 g_rope[TT * 32];         // (sin, cos) per (t, d)
__device__ int   g_tix  [NTOK * 2];
__device__ float g_tgate[NTOK * 2];
__device__ int   g_expert_tok [NEXP * CAP];    // zero-init
__device__ float g_expert_gate[NEXP * CAP];    // zero-init

// transposed split weights: [N][K] K-contiguous
__device__ __align__(128) bf16 g_wqkvTh[3 * DD * DD];
__device__ __align__(128) bf16 g_wqkvTl[3 * DD * DD];
__device__ __align__(128) bf16 g_wprojTh[DD * DD];
__device__ __align__(128) bf16 g_wprojTl[DD * DD];
__device__ __align__(128) bf16 g_w1th[NEXP * DFF * DD];   // hi only (2-term up)
__device__ __align__(128) bf16 g_w2th[NEXP * DD * DFF];   // hi only (2-term down)
// activations for MoE (hc split)
__device__ __align__(128) bf16 g_hcHi[NEXP * CAP * DFF];
__device__ __align__(128) bf16 g_hcLo[NEXP * CAP * DFF];

// ---------------- small helpers ----------------
__device__ __forceinline__ float warpReduceSum(float v) {
    v += __shfl_xor_sync(0xffffffffu, v, 16);
    v += __shfl_xor_sync(0xffffffffu, v, 8);
    v += __shfl_xor_sync(0xffffffffu, v, 4);
    v += __shfl_xor_sync(0xffffffffu, v, 2);
    v += __shfl_xor_sync(0xffffffffu, v, 1);
    return v;
}
__device__ __forceinline__ uint32_t smem_u32(const void* p) {
    uint32_t a;
    asm("{ .reg .u64 t; cvta.to.shared.u64 t, %1; cvt.u32.u64 %0, t; }" : "=r"(a) : "l"(p));
    return a;
}
__device__ __forceinline__ uint32_t swz(uint32_t o) { return o ^ ((o >> 3) & 0x70); }
__device__ __forceinline__ void cpa16(uint32_t s, const void* g) {
    asm volatile("cp.async.cg.shared.global [%0], [%1], 16;" :: "r"(s), "l"(g));
}
__device__ __forceinline__ uint4 ldsm4(uint32_t a) {
    uint4 r;
    asm volatile("ldmatrix.sync.aligned.m8n8.x4.shared.b16 {%0,%1,%2,%3}, [%4];"
                 : "=r"(r.x), "=r"(r.y), "=r"(r.z), "=r"(r.w) : "r"(a));
    return r;
}
__device__ __forceinline__ void mma16816(float* d, const uint4& a, uint32_t b0, uint32_t b1) {
    asm volatile(
        "mma.sync.aligned.m16n8k16.row.col.f32.bf16.bf16.f32 "
        "{%0,%1,%2,%3}, {%4,%5,%6,%7}, {%8,%9}, {%0,%1,%2,%3};"
        : "+f"(d[0]), "+f"(d[1]), "+f"(d[2]), "+f"(d[3])
        : "r"(a.x), "r"(a.y), "r"(a.z), "r"(a.w), "r"(b0), "r"(b1));
}
__device__ __forceinline__ void split2(float v, bf16& h, bf16& l) {
    h = __float2bfloat16(v);
    l = __float2bfloat16(v - __bfloat162float(h));
}
__device__ __forceinline__ uint32_t pack2bf(bf16 a, bf16 b) {
    return (uint32_t)__bfloat16_as_ushort(a) | ((uint32_t)__bfloat16_as_ushort(b) << 16);
}
__device__ __forceinline__ void sts128(uint32_t addr, uint4 v) {
    asm volatile("st.shared.v4.b32 [%0], {%1,%2,%3,%4};"
                 :: "r"(addr), "r"(v.x), "r"(v.y), "r"(v.z), "r"(v.w));
}
__device__ __forceinline__ void sts16(uint32_t addr, uint16_t v) {
    asm volatile("st.shared.u16 [%0], %1;" :: "r"(addr), "h"((unsigned short)v));
}

// ---------------- RoPE sin/cos table ----------------
__global__ void rope_table_kernel()
{
    int idx = blockIdx.x * blockDim.x + threadIdx.x;   // 0 .. TT*32-1
    int t = idx >> 5, d = idx & 31;
    float inv = expf((float)d * -0.28782313662425576f);
    float ang = (float)t * inv;
    float sv, cv;
    sincosf(ang, &sv, &cv);
    g_rope[idx] = make_float2(sv, cv);
}

// ---------------- LayerNorm (emits optional fp32 + split bf16) ----------------
__launch_bounds__(256)
__global__ void ln_kernel(const float* __restrict__ x,
                          const float* __restrict__ gamma,
                          const float* __restrict__ beta,
                          float* __restrict__ yf,
                          bf16* __restrict__ yh, bf16* __restrict__ yl)
{
    int row = blockIdx.x;
    int tid = threadIdx.x;
    int lane = tid & 31, wid = tid >> 5;
    const float* xr = x + (size_t)row * DD;
    __shared__ float red[8];

    float v[4];
#pragma unroll
    for (int i = 0; i < 4; i++) v[i] = xr[tid + i * 256];

    float s = v[0] + v[1] + v[2] + v[3];
    s = warpReduceSum(s);
    if (lane == 0) red[wid] = s;
    __syncthreads();
    float tot = red[0] + red[1] + red[2] + red[3] + red[4] + red[5] + red[6] + red[7];
    float mean = tot * (1.0f / 1024.0f);
    __syncthreads();

    float sq = 0.f;
#pragma unroll
    for (int i = 0; i < 4; i++) { float d = v[i] - mean; sq += d * d; }
    sq = warpReduceSum(sq);
    if (lane == 0) red[wid] = sq;
    __syncthreads();
    float vtot = red[0] + red[1] + red[2] + red[3] + red[4] + red[5] + red[6] + red[7];
    float rstd = rsqrtf(vtot * (1.0f / 1024.0f) + 1e-5f);

#pragma unroll
    for (int i = 0; i < 4; i++) {
        int d = tid + i * 256;
        float o = (v[i] - mean) * rstd * gamma[d] + beta[d];
        if (yf) yf[(size_t)row * DD + d] = o;
        bf16 h, l; split2(o, h, l);
        yh[(size_t)row * DD + d] = h;
        yl[(size_t)row * DD + d] = l;
    }
}

// ---------------- Flash attention on tensor cores (split bf16, fp32 softmax) ----
#define ATT_SMEM 65536

__launch_bounds__(256, 2)
__global__ void attn_mma_kernel(const bf16* __restrict__ qkvH,
                                const bf16* __restrict__ qkvL,
                                bf16* __restrict__ aoH, bf16* __restrict__ aoL)
{
    extern __shared__ __align__(128) char dsm[];
    const uint32_t sb = smem_u32(dsm);
    const int tid = threadIdx.x, lane = tid & 31, wid = tid >> 5;
    const int qb = blockIdx.x, h = blockIdx.y, b = blockIdx.z;
    const int warp_m = wid * 16;

    // ---- load Q tile (pre-split bf16, direct copy into swizzled smem) ----
    {
        const bf16* qh = qkvH + (size_t)(b * TT + qb * 128) * 3072 + h * DHH;
        const bf16* ql = qkvL + (size_t)(b * TT + qb * 128) * 3072 + h * DHH;
        for (int i = tid; i < 1024; i += 256) {
            int row = i >> 3, c8 = (i & 7) * 8;
            uint4 vh = *(const uint4*)(qh + (size_t)row * 3072 + c8);
            uint4 vl = *(const uint4*)(ql + (size_t)row * 3072 + c8);
            uint32_t off = swz(row * 128 + c8 * 2);
            sts128(sb + off, vh);
            sts128(sb + 16384 + off, vl);
        }
    }

    float oc[8][4];
#pragma unroll
    for (int q = 0; q < 8; q++)
#pragma unroll
        for (int j = 0; j < 4; j++) oc[q][j] = 0.f;
    float m0 = -1e30f, m1 = -1e30f, l0s = 0.f, l1s = 0.f;

    const int r0g = qb * 128 + warp_m + (lane >> 2);
    const int r1g = r0g + 8;
    const int nkt = 2 * (qb + 1);

    for (int kt = 0; kt < nkt; kt++) {
        __syncthreads();
        {
            size_t kb0 = (size_t)(b * TT + kt * 64) * 3072 + DD + h * DHH;
            // K tile 64x64
            for (int i = tid; i < 512; i += 256) {
                int row = i >> 3, c8 = (i & 7) * 8;
                uint4 vh = *(const uint4*)(qkvH + kb0 + (size_t)row * 3072 + c8);
                uint4 vl = *(const uint4*)(qkvL + kb0 + (size_t)row * 3072 + c8);
                uint32_t off = swz(row * 128 + c8 * 2);
                sts128(sb + 32768 + off, vh);
                sts128(sb + 40960 + off, vl);
            }
            // V tile transposed
            size_t vb0 = kb0 + DD;
            for (int i = tid; i < 512; i += 256) {
                int row = i >> 3, c8 = (i & 7) * 8;
                uint4 vh = *(const uint4*)(qkvH + vb0 + (size_t)row * 3072 + c8);
                uint4 vl = *(const uint4*)(qkvL + vb0 + (size_t)row * 3072 + c8);
                const uint16_t* ph = (const uint16_t*)&vh;
                const uint16_t* pl = (const uint16_t*)&vl;
#pragma unroll
                for (int j = 0; j < 8; j++) {
                    uint32_t voff = swz((c8 + j) * 128 + row * 2);
                    sts16(sb + 49152 + voff, ph[j]);
                    sts16(sb + 57344 + voff, pl[j]);
                }
            }
        }
        __syncthreads();

        float sc[8][4];
#pragma unroll
        for (int q = 0; q < 8; q++)
#pragma unroll
            for (int j = 0; j < 4; j++) sc[q][j] = 0.f;
#pragma unroll
        for (int k16 = 0; k16 < 4; k16++) {
            int kb = k16 * 32 + (lane >> 4) * 16;
            uint32_t aoff = swz((warp_m + (lane & 15)) * 128 + kb);
            uint4 Ah = ldsm4(sb + aoff);
            uint4 Al = ldsm4(sb + 16384 + aoff);
#pragma unroll
            for (int q = 0; q < 4; q++) {
                uint32_t boff = swz((q * 16 + (lane & 15)) * 128 + kb);
                uint4 Bh = ldsm4(sb + 32768 + boff);
                uint4 Bl = ldsm4(sb + 40960 + boff);
                mma16816(sc[2 * q],     Ah, Bh.x, Bh.z);
                mma16816(sc[2 * q + 1], Ah, Bh.y, Bh.w);
                mma16816(sc[2 * q],     Al, Bh.x, Bh.z);
                mma16816(sc[2 * q + 1], Al, Bh.y, Bh.w);
                mma16816(sc[2 * q],     Ah, Bl.x, Bl.z);
                mma16816(sc[2 * q + 1], Ah, Bl.y, Bl.w);
            }
        }

        const bool dmask = (64 * kt + 63 > qb * 128 + warp_m);
        float mt0 = -1e30f, mt1 = -1e30f;
#pragma unroll
        for (int q = 0; q < 8; q++) {
            int col = kt * 64 + q * 8 + 2 * (lane & 3);
            if (dmask) {
                sc[q][0] = (col     <= r0g) ? sc[q][0] * 0.125f : -1e30f;
                sc[q][1] = (col + 1 <= r0g) ? sc[q][1] * 0.125f : -1e30f;
                sc[q][2] = (col     <= r1g) ? sc[q][2] * 0.125f : -1e30f;
                sc[q][3] = (col + 1 <= r1g) ? sc[q][3] * 0.125f : -1e30f;
            } else {
                sc[q][0] *= 0.125f; sc[q][1] *= 0.125f;
                sc[q][2] *= 0.125f; sc[q][3] *= 0.125f;
            }
            mt0 = fmaxf(mt0, fmaxf(sc[q][0], sc[q][1]));
            mt1 = fmaxf(mt1, fmaxf(sc[q][2], sc[q][3]));
        }
        mt0 = fmaxf(mt0, __shfl_xor_sync(0xffffffffu, mt0, 1));
        mt0 = fmaxf(mt0, __shfl_xor_sync(0xffffffffu, mt0, 2));
        mt1 = fmaxf(mt1, __shfl_xor_sync(0xffffffffu, mt1, 1));
        mt1 = fmaxf(mt1, __shfl_xor_sync(0xffffffffu, mt1, 2));
        float mn0 = fmaxf(m0, mt0), mn1 = fmaxf(m1, mt1);
        float e0 = __expf(m0 - mn0), e1 = __expf(m1 - mn1);
        m0 = mn0; m1 = mn1;
        float ls0 = 0.f, ls1 = 0.f;
#pragma unroll
        for (int q = 0; q < 8; q++) {
            sc[q][0] = __expf(sc[q][0] - mn0); ls0 += sc[q][0];
            sc[q][1] = __expf(sc[q][1] - mn0); ls0 += sc[q][1];
            sc[q][2] = __expf(sc[q][2] - mn1); ls1 += sc[q][2];
            sc[q][3] = __expf(sc[q][3] - mn1); ls1 += sc[q][3];
        }
        ls0 += __shfl_xor_sync(0xffffffffu, ls0, 1);
        ls0 += __shfl_xor_sync(0xffffffffu, ls0, 2);
        ls1 += __shfl_xor_sync(0xffffffffu, ls1, 1);
        ls1 += __shfl_xor_sync(0xffffffffu, ls1, 2);
        l0s = l0s * e0 + ls0;
        l1s = l1s * e1 + ls1;
#pragma unroll
        for (int q = 0; q < 8; q++) {
            oc[q][0] *= e0; oc[q][1] *= e0;
            oc[q][2] *= e1; oc[q][3] *= e1;
        }

#pragma unroll
        for (int kk = 0; kk < 4; kk++) {
            bf16 ph[8], pl[8];
            split2(sc[2 * kk][0],     ph[0], pl[0]);
            split2(sc[2 * kk][1],     ph[1], pl[1]);
            split2(sc[2 * kk][2],     ph[2], pl[2]);
            split2(sc[2 * kk][3],     ph[3], pl[3]);
            split2(sc[2 * kk + 1][0], ph[4], pl[4]);
            split2(sc[2 * kk + 1][1], ph[5], pl[5]);
            split2(sc[2 * kk + 1][2], ph[6], pl[6]);
            split2(sc[2 * kk + 1][3], ph[7], pl[7]);
            uint4 Ah = make_uint4(pack2bf(ph[0], ph[1]), pack2bf(ph[2], ph[3]),
                                  pack2bf(ph[4], ph[5]), pack2bf(ph[6], ph[7]));
            uint4 Al = make_uint4(pack2bf(pl[0], pl[1]), pack2bf(pl[2], pl[3]),
                                  pack2bf(pl[4], pl[5]), pack2bf(pl[6], pl[7]));
            int kb = kk * 32 + (lane >> 4) * 16;
#pragma unroll
            for (int q = 0; q < 4; q++) {
                uint32_t boff = swz((q * 16 + (lane & 15)) * 128 + kb);
                uint4 Vh = ldsm4(sb + 49152 + boff);
                uint4 Vl = ldsm4(sb + 57344 + boff);
                mma16816(oc[2 * q],     Ah, Vh.x, Vh.z);
                mma16816(oc[2 * q + 1], Ah, Vh.y, Vh.w);
                mma16816(oc[2 * q],     Al, Vh.x, Vh.z);
                mma16816(oc[2 * q + 1], Al, Vh.y, Vh.w);
                mma16816(oc[2 * q],     Ah, Vl.x, Vl.z);
                mma16816(oc[2 * q + 1], Ah, Vl.y, Vl.w);
            }
        }
    }

    float inv0 = 1.0f / l0s, inv1 = 1.0f / l1s;
    int tok0 = b * TT + qb * 128 + warp_m + (lane >> 2);
#pragma unroll
    for (int q = 0; q < 8; q++) {
        int c = h * DHH + q * 8 + 2 * (lane & 3);
        bf16 h0, l0, h1, l1;
        split2(oc[q][0] * inv0, h0, l0);
        split2(oc[q][1] * inv0, h1, l1);
        *(uint32_t*)&aoH[(size_t)tok0 * DD + c] = pack2bf(h0, h1);
        *(uint32_t*)&aoL[(size_t)tok0 * DD + c] = pack2bf(l0, l1);
        split2(oc[q][2] * inv1, h0, l0);
        split2(oc[q][3] * inv1, h1, l1);
        *(uint32_t*)&aoH[(size_t)(tok0 + 8) * DD + c] = pack2bf(h0, h1);
        *(uint32_t*)&aoL[(size_t)(tok0 + 8) * DD + c] = pack2bf(l0, l1);
    }
}

// ---------------- Router ----------------
__launch_bounds__(256)
__global__ void router_kernel(const float* __restrict__ h2,
                              const float* __restrict__ noise,
                              const float* __restrict__ w_rl,
                              const float* __restrict__ b_rl,
                              const float* __restrict__ w_rn,
                              const float* __restrict__ b_rn)
{
    int n = blockIdx.x;
    int tid = threadIdx.x;
    int lane = tid & 31, wid = tid >> 5;
    const float* hr = h2 + (size_t)n * DD;

    float aL[8], aN[8];
#pragma unroll
    for (int e = 0; e < 8; e++) { aL[e] = 0.f; aN[e] = 0.f; }

    for (int d = tid; d < DD; d += 256) {
        float hv = hr[d];
        const float4* rl4 = (const float4*)(w_rl + (size_t)d * 8);
        const float4* rn4 = (const float4*)(w_rn + (size_t)d * 8);
        float4 l0 = rl4[0], l1 = rl4[1];
        float4 n0 = rn4[0], n1 = rn4[1];
        aL[0] += hv * l0.x; aL[1] += hv * l0.y; aL[2] += hv * l0.z; aL[3] += hv * l0.w;
        aL[4] += hv * l1.x; aL[5] += hv * l1.y; aL[6] += hv * l1.z; aL[7] += hv * l1.w;
        aN[0] += hv * n0.x; aN[1] += hv * n0.y; aN[2] += hv * n0.z; aN[3] += hv * n0.w;
        aN[4] += hv * n1.x; aN[5] += hv * n1.y; aN[6] += hv * n1.z; aN[7] += hv * n1.w;
    }
#pragma unroll
    for (int e = 0; e < 8; e++) { aL[e] = warpReduceSum(aL[e]); aN[e] = warpReduceSum(aN[e]); }

    __shared__ float sL[8][8], sN[8][8];
    if (lane == 0) {
#pragma unroll
        for (int e = 0; e < 8; e++) { sL[wid][e] = aL[e]; sN[wid][e] = aN[e]; }
    }
    __syncthreads();

    if (tid == 0) {
        float v0 = -1e38f, v1 = -1e38f;
        int i0 = 0, i1 = 0;
#pragma unroll
        for (int e = 0; e < 8; e++) {
            float L = 0.f, Nn = 0.f;
#pragma unroll
            for (int w = 0; w < 8; w++) { L += sL[w][e]; Nn += sN[w][e]; }
            float spin = Nn + b_rn[e];
            float sp = fmaxf(spin, 0.f) + log1pf(expf(-fabsf(spin)));
            float v = L + b_rl[e] + noise[(size_t)n * 8 + e] * sp;
            if (v > v0)      { v1 = v0; i1 = i0; v0 = v; i0 = e; }
            else if (v > v1) { v1 = v;  i1 = e; }
        }
        float ex = expf(v1 - v0);
        float inv = 1.0f / (1.0f + ex);
        g_tix[n * 2]     = i0;
        g_tix[n * 2 + 1] = i1;
        g_tgate[n * 2]     = inv;
        g_tgate[n * 2 + 1] = ex * inv;
    }
}

// ---------------- Expert assignment ----------------
__launch_bounds__(256)
__global__ void assign_kernel()
{
    int e = blockIdx.x;
    int tid = threadIdx.x;
    int lane = tid & 31, wid = tid >> 5;
    __shared__ int warpsum[8];

    int flags[8];
    int cnt = 0;
#pragma unroll
    for (int i = 0; i < 8; i++) {
        int tok = tid * 8 + i;
        int f = 0;
        if (g_tix[tok * 2] == e) f = 1;
        else if (g_tix[tok * 2 + 1] == e) f = 2;
        flags[i] = f;
        cnt += (f != 0);
    }
    int incl = cnt;
#pragma unroll
    for (int off = 1; off < 32; off <<= 1) {
        int v = __shfl_up_sync(0xffffffffu, incl, off);
        if (lane >= off) incl += v;
    }
    if (lane == 31) warpsum[wid] = incl;
    __syncthreads();
    int wbase = 0;
    for (int w = 0; w < wid; w++) wbase += warpsum[w];
    int base = wbase + incl - cnt;

#pragma unroll
    for (int i = 0; i < 8; i++) {
        if (flags[i]) {
            if (base < CAP) {
                int tok = tid * 8 + i;
                g_expert_tok[e * CAP + base]  = tok;
                g_expert_gate[e * CAP + base] = g_tgate[tok * 2 + (flags[i] - 1)];
            }
            base++;
        }
    }
}

// ---------------- weight transpose + split (vectorized 4B stores) ----------------
// W [e][K][N] fp32 -> Oh (and optionally Ol) [e][N][K] bf16
__global__ void conv_w_kernel(const float* __restrict__ W,
                              bf16* __restrict__ Oh, bf16* __restrict__ Ol,
                              int K, int N)
{
    __shared__ float tile[32][33];
    int e = blockIdx.z;
    const float* Wp = W + (size_t)e * K * N;
    size_t ob = (size_t)e * K * N;
    int n0 = blockIdx.x * 32, k0 = blockIdx.y * 32;
    int tx = threadIdx.x, ty = threadIdx.y;   // 32 x 8
#pragma unroll
    for (int i = 0; i < 32; i += 8)
        tile[ty + i][tx] = Wp[(size_t)(k0 + ty + i) * N + n0 + tx];
    __syncthreads();
    int tid = ty * 32 + tx;
    int kp = tid & 15;
    int nl0 = tid >> 4;
#pragma unroll
    for (int it = 0; it < 2; it++) {
        int nl = nl0 + it * 16;
        float v0 = tile[2 * kp][nl];
        float v1 = tile[2 * kp + 1][nl];
        bf16 h0, l0, h1, l1;
        split2(v0, h0, l0);
        split2(v1, h1, l1);
        size_t o = ob + (size_t)(n0 + nl) * K + k0 + 2 * kp;
        *(uint32_t*)&Oh[o] = pack2bf(h0, h1);
        if (Ol) *(uint32_t*)&Ol[o] = pack2bf(l0, l1);
    }
}

// ---------------- split-bf16 tensor-core GEMM (proven structure) ----------------
// C[M][N] = A[M][K] @ B[N][K]^T.
// S3=1: 3-term split (hi*hi + lo*hi + hi*lo).  S3=0: 2-term (hi*hi + lo*hi), B hi-only.
// MODE 0: qkv = A@B with fused table-RoPE on q,k, split-stored (Oh/Ol = qkvHi/Lo, N=3072)
// MODE 1: C = C2 = X + A@B                       (attn proj + residual)
// MODE 2: hc = relu(gather(A)@B + b1[e])         (expert up; A rows via g_expert_tok)
// MODE 3: out[tok] += (A@B + b2[e]) * gate       (expert down, atomic scatter)
#define GEMM_SMEM (2 * 65536)

template<bool S3>
__device__ __forceinline__ void compute_stage(uint32_t sb, int warp_m, int warp_n,
                                              int lane, float acc[2][8][4])
{
    int lr = lane & 15, lc = lane >> 4;
#pragma unroll
    for (int k16 = 0; k16 < 4; k16++) {
        int kb = k16 * 32 + lc * 16;
        uint32_t a0o = swz((warp_m + lr) * 128 + kb);
        uint32_t a1o = swz((warp_m + 16 + lr) * 128 + kb);
        uint4 Ah0 = ldsm4(sb + a0o);
        uint4 Ah1 = ldsm4(sb + a1o);
        uint4 Al0 = ldsm4(sb + 16384 + a0o);
        uint4 Al1 = ldsm4(sb + 16384 + a1o);
#pragma unroll
        for (int q = 0; q < 4; q++) {
            uint32_t off = swz((warp_n + q * 16 + lr) * 128 + kb);
            uint4 Bh = ldsm4(sb + 32768 + off);
            mma16816(acc[0][q * 2 + 0], Ah0, Bh.x, Bh.z);
            mma16816(acc[0][q * 2 + 1], Ah0, Bh.y, Bh.w);
            mma16816(acc[1][q * 2 + 0], Ah1, Bh.x, Bh.z);
            mma16816(acc[1][q * 2 + 1], Ah1, Bh.y, Bh.w);
            mma16816(acc[0][q * 2 + 0], Al0, Bh.x, Bh.z);
            mma16816(acc[0][q * 2 + 1], Al0, Bh.y, Bh.w);
            mma16816(acc[1][q * 2 + 0], Al1, Bh.x, Bh.z);
            mma16816(acc[1][q * 2 + 1], Al1, Bh.y, Bh.w);
            if (S3) {
                uint4 Bl = ldsm4(sb + 49152 + off);
                mma16816(acc[0][q * 2 + 0], Ah0, Bl.x, Bl.z);
                mma16816(acc[0][q * 2 + 1], Ah0, Bl.y, Bl.w);
                mma16816(acc[1][q * 2 + 0], Ah1, Bl.x, Bl.z);
                mma16816(acc[1][q * 2 + 1], Ah1, Bl.y, Bl.w);
            }
        }
    }
}

template<int MODE, bool S3>
__launch_bounds__(256)
__global__ void gemm_bf16(const bf16* __restrict__ Ah, const bf16* __restrict__ Al,
                          const bf16* __restrict__ Bh, const bf16* __restrict__ Bl,
                          float* __restrict__ C, float* __restrict__ C2,
                          const float* __restrict__ Xres,
                          const float* __restrict__ bias,
                          bf16* __restrict__ Oh, bf16* __restrict__ Ol,
                          int K, int N)
{
    extern __shared__ __align__(128) char dsm[];
    const uint32_t sb0 = smem_u32(dsm);
    const int tid = threadIdx.x, lane = tid & 31, wid = tid >> 5;
    const int e = blockIdx.z;
    const int m0 = blockIdx.y * 128, n0 = blockIdx.x * 128;
    const int warp_m = (wid >> 1) * 32, warp_n = (wid & 1) * 64;

    const size_t rK = (size_t)K * 2;   // bytes per row
    const char* pAh;
    const char* pAl;
    if (MODE == 2) { pAh = (const char*)Ah; pAl = (const char*)Al; }  // token-indirect rows
    else if (MODE == 3) {
        pAh = (const char*)(Ah + ((size_t)e * CAP + m0) * K);
        pAl = (const char*)(Al + ((size_t)e * CAP + m0) * K);
    } else {
        pAh = (const char*)(Ah + (size_t)m0 * K);
        pAl = (const char*)(Al + (size_t)m0 * K);
    }
    const char* pBh = (const char*)(Bh + ((MODE >= 2) ? (size_t)e * N * K : 0) + (size_t)n0 * K);
    const char* pBl = (const char*)(S3 ? (Bl + ((MODE >= 2) ? (size_t)e * N * K : 0) + (size_t)n0 * K) : nullptr);
    const int NC = K >> 6;

    auto issue = [&](int c) {
        uint32_t sbuf = sb0 + (c & 1) * 65536;
        int kb = c * 128;
#pragma unroll
        for (int i = 0; i < 4; i++) {
            int idx = tid + i * 256;
            int row = idx >> 3;
            int c16 = (idx & 7) * 16;
            uint32_t sw = swz(row * 128 + c16);
            size_t goA;
            if (MODE == 2) {
                int tok = g_expert_tok[e * CAP + m0 + row];
                goA = (size_t)tok * rK + kb + c16;
            } else {
                goA = (size_t)row * rK + kb + c16;
            }
            size_t goB = (size_t)row * rK + kb + c16;
            cpa16(sbuf + sw,         pAh + goA);
            cpa16(sbuf + 16384 + sw, pAl + goA);
            cpa16(sbuf + 32768 + sw, pBh + goB);
            if (S3) cpa16(sbuf + 49152 + sw, pBl + goB);
        }
        asm volatile("cp.async.commit_group;" ::: "memory");
    };

    float acc[2][8][4];
#pragma unroll
    for (int a = 0; a < 2; a++)
#pragma unroll
        for (int b = 0; b < 8; b++)
#pragma unroll
            for (int c = 0; c < 4; c++) acc[a][b][c] = 0.f;

    issue(0);
    for (int c = 0; c < NC; c++) {
        if (c + 1 < NC) {
            issue(c + 1);
            asm volatile("cp.async.wait_group 1;" ::: "memory");
        } else {
            asm volatile("cp.async.wait_group 0;" ::: "memory");
        }
        __syncthreads();
        compute_stage<S3>(sb0 + (c & 1) * 65536, warp_m, warp_n, lane, acc);
        __syncthreads();
    }

    // ---- MODE 0 epilogue: fused table-RoPE + split-store qkv ----
    if (MODE == 0) {
#pragma unroll
        for (int mt = 0; mt < 2; mt++) {
#pragma unroll
            for (int rh = 0; rh < 2; rh++) {
                int gr = m0 + warp_m + mt * 16 + rh * 8 + (lane >> 2);
                int t = gr & (TT - 1);
#pragma unroll
                for (int nt = 0; nt < 4; nt++) {
                    int gc = n0 + warp_n + nt * 8 + (lane & 3) * 2;
                    float a0 = acc[mt][nt][rh * 2 + 0];
                    float a1 = acc[mt][nt][rh * 2 + 1];
                    float b0 = acc[mt][nt + 4][rh * 2 + 0];
                    float b1 = acc[mt][nt + 4][rh * 2 + 1];
                    if (gc < 2048) {   // q or k section: apply RoPE (pairs d, d+32)
                        int d0 = gc & 63;        // < 32 guaranteed (nt < 4)
                        float2 sc0 = g_rope[t * 32 + d0];
                        float2 sc1 = g_rope[t * 32 + d0 + 1];
                        float na0 = a0 * sc0.y - b0 * sc0.x, nb0 = b0 * sc0.y + a0 * sc0.x;
                        float na1 = a1 * sc1.y - b1 * sc1.x, nb1 = b1 * sc1.y + a1 * sc1.x;
                        a0 = na0; b0 = nb0; a1 = na1; b1 = nb1;
                    }
                    bf16 h0, l0, h1, l1;
                    size_t ix = (size_t)gr * 3072 + gc;
                    split2(a0, h0, l0); split2(a1, h1, l1);
                    *(uint32_t*)&Oh[ix] = pack2bf(h0, h1);
                    *(uint32_t*)&Ol[ix] = pack2bf(l0, l1);
                    split2(b0, h0, l0); split2(b1, h1, l1);
                    *(uint32_t*)&Oh[ix + 32] = pack2bf(h0, h1);
                    *(uint32_t*)&Ol[ix + 32] = pack2bf(l0, l1);
                }
            }
        }
        return;
    }

    // ---- generic epilogue (MODE 1/2/3) ----
#pragma unroll
    for (int mt = 0; mt < 2; mt++) {
#pragma unroll
        for (int rh = 0; rh < 2; rh++) {
            int gr = m0 + warp_m + mt * 16 + rh * 8 + (lane >> 2);
            int tok = 0; float gt = 0.f;
            if (MODE == 3) {
                int slot = e * CAP + gr;
                tok = g_expert_tok[slot];
                gt = g_expert_gate[slot];
            }
#pragma unroll
            for (int nt = 0; nt < 8; nt++) {
                int gc = n0 + warp_n + nt * 8 + (lane & 3) * 2;
                float d0 = acc[mt][nt][rh * 2 + 0];
                float d1 = acc[mt][nt][rh * 2 + 1];
                if (MODE == 1) {
                    size_t ix = (size_t)gr * N + gc;
                    float2 xv = *(const float2*)&Xres[ix];
                    float2 v = make_float2(d0 + xv.x, d1 + xv.y);
                    *(float2*)&C[ix] = v;
                    *(float2*)&C2[ix] = v;
                } else if (MODE == 2) {
                    float v0 = fmaxf(d0 + bias[(size_t)e * N + gc], 0.f);
                    float v1 = fmaxf(d1 + bias[(size_t)e * N + gc + 1], 0.f);
                    bf16 h0, l0, h1, l1;
                    split2(v0, h0, l0);
                    split2(v1, h1, l1);
                    size_t ix = ((size_t)e * CAP + gr) * (size_t)N + gc;
                    *(uint32_t*)&Oh[ix] = pack2bf(h0, h1);
                    *(uint32_t*)&Ol[ix] = pack2bf(l0, l1);
                } else {
                    if (gt != 0.f) {
                        float v0 = (d0 + bias[(size_t)e * N + gc]) * gt;
                        float v1 = (d1 + bias[(size_t)e * N + gc + 1]) * gt;
                        atomicAdd(&C2[(size_t)tok * DD + gc], v0);
                        atomicAdd(&C2[(size_t)tok * DD + gc + 1], v1);
                    }
                }
            }
        }
    }
}

// ---------------- launch ----------------
extern "C" void kernel_launch(void* const* d_in, const int* in_sizes, int n_in,
                              void* d_out, int out_size)
{
    const float* x      = (const float*)d_in[0];
    const float* noise  = (const float*)d_in[1];
    const float* ln1_g  = (const float*)d_in[2];
    const float* ln1_b  = (const float*)d_in[3];
    const float* ln2_g  = (const float*)d_in[4];
    const float* ln2_b  = (const float*)d_in[5];
    const float* w_qkv  = (const float*)d_in[6];
    const float* w_proj = (const float*)d_in[7];
    const float* w_rl   = (const float*)d_in[8];
    const float* b_rl   = (const float*)d_in[9];
    const float* w_rn   = (const float*)d_in[10];
    const float* b_rn   = (const float*)d_in[11];
    const float* w1     = (const float*)d_in[12];
    const float* b1     = (const float*)d_in[13];
    const float* w2     = (const float*)d_in[14];
    const float* b2     = (const float*)d_in[15];
    float* out = (float*)d_out;

    float *p_x2, *p_h2;
    bf16 *p_hH, *p_hL, *p_qkvH, *p_qkvL, *p_aoH, *p_aoL, *p_h2H, *p_h2L;
    bf16 *p_wqkvTh, *p_wqkvTl, *p_wprojTh, *p_wprojTl;
    bf16 *p_w1th, *p_w2th;
    bf16 *p_hcH, *p_hcL;
    cudaGetSymbolAddress((void**)&p_x2,  g_x2);
    cudaGetSymbolAddress((void**)&p_h2,  g_h2);
    cudaGetSymbolAddress((void**)&p_hH,  g_hHi);
    cudaGetSymbolAddress((void**)&p_hL,  g_hLo);
    cudaGetSymbolAddress((void**)&p_qkvH, g_qkvHi);
    cudaGetSymbolAddress((void**)&p_qkvL, g_qkvLo);
    cudaGetSymbolAddress((void**)&p_aoH, g_aoHi);
    cudaGetSymbolAddress((void**)&p_aoL, g_aoLo);
    cudaGetSymbolAddress((void**)&p_h2H, g_h2Hi);
    cudaGetSymbolAddress((void**)&p_h2L, g_h2Lo);
    cudaGetSymbolAddress((void**)&p_wqkvTh, g_wqkvTh);
    cudaGetSymbolAddress((void**)&p_wqkvTl, g_wqkvTl);
    cudaGetSymbolAddress((void**)&p_wprojTh, g_wprojTh);
    cudaGetSymbolAddress((void**)&p_wprojTl, g_wprojTl);
    cudaGetSymbolAddress((void**)&p_w1th, g_w1th);
    cudaGetSymbolAddress((void**)&p_w2th, g_w2th);
    cudaGetSymbolAddress((void**)&p_hcH, g_hcHi);
    cudaGetSymbolAddress((void**)&p_hcL, g_hcLo);

    cudaFuncSetAttribute((const void*)gemm_bf16<0, true>,  cudaFuncAttributeMaxDynamicSharedMemorySize, GEMM_SMEM);
    cudaFuncSetAttribute((const void*)gemm_bf16<1, true>,  cudaFuncAttributeMaxDynamicSharedMemorySize, GEMM_SMEM);
    cudaFuncSetAttribute((const void*)gemm_bf16<2, false>, cudaFuncAttributeMaxDynamicSharedMemorySize, GEMM_SMEM);
    cudaFuncSetAttribute((const void*)gemm_bf16<3, false>, cudaFuncAttributeMaxDynamicSharedMemorySize, GEMM_SMEM);
    cudaFuncSetAttribute(attn_mma_kernel, cudaFuncAttributeMaxDynamicSharedMemorySize, ATT_SMEM);

    // rope table + weight transpose/split (independent prologue work)
    rope_table_kernel<<<TT * 32 / 256, 256>>>();
    conv_w_kernel<<<dim3(3 * DD / 32, DD / 32, 1), dim3(32, 8)>>>(w_qkv, p_wqkvTh, p_wqkvTl, DD, 3 * DD);
    conv_w_kernel<<<dim3(DD / 32, DD / 32, 1), dim3(32, 8)>>>(w_proj, p_wprojTh, p_wprojTl, DD, DD);
    conv_w_kernel<<<dim3(DFF / 32, DD / 32, NEXP), dim3(32, 8)>>>(w1, p_w1th, nullptr, DD, DFF);
    conv_w_kernel<<<dim3(DD / 32, DFF / 32, NEXP), dim3(32, 8)>>>(w2, p_w2th, nullptr, DFF, DD);

    // 1. h = LN1(x)  (split only)
    ln_kernel<<<NTOK, 256>>>(x, ln1_g, ln1_b, nullptr, p_hH, p_hL);
    // 2. qkv = h @ w_qkv + fused table-RoPE, split-stored   [tensor, 3-term]
    gemm_bf16<0, true><<<dim3(24, 16, 1), 256, GEMM_SMEM>>>(p_hH, p_hL, p_wqkvTh, p_wqkvTl,
                                                            nullptr, nullptr, nullptr, nullptr,
                                                            p_qkvH, p_qkvL, DD, 3 * DD);
    // 3. attention [tensor, 3-term] (reads pre-split qkv)
    attn_mma_kernel<<<dim3(8, HH, BB), 256, ATT_SMEM>>>(p_qkvH, p_qkvL, p_aoH, p_aoL);
    // 4. x2 = x + ao @ w_proj  (seeds out)   [tensor, 3-term]
    gemm_bf16<1, true><<<dim3(8, 16, 1), 256, GEMM_SMEM>>>(p_aoH, p_aoL, p_wprojTh, p_wprojTl,
                                                           p_x2, out, x, nullptr,
                                                           nullptr, nullptr, DD, DD);
    // 5. h2 = LN2(x2)  (fp32 + split)
    ln_kernel<<<NTOK, 256>>>(p_x2, ln2_g, ln2_b, p_h2, p_h2H, p_h2L);
    // 6. router
    router_kernel<<<NTOK, 256>>>(p_h2, noise, w_rl, b_rl, w_rn, b_rn);
    // 7. capacity assignment
    assign_kernel<<<NEXP, 256>>>();
    // 8. expert up (gather fused): hc = relu(h2[tok] @ w1 + b1)   [tensor, 2-term]
    gemm_bf16<2, false><<<dim3(DFF / 128, CAP / 128, NEXP), 256, GEMM_SMEM>>>(
        p_h2H, p_h2L, p_w1th, nullptr, nullptr, nullptr, nullptr, b1, p_hcH, p_hcL, DD, DFF);
    // 9. expert down: out += (hc @ w2 + b2) * gate   [tensor, 2-term]
    gemm_bf16<3, false><<<dim3(DD / 128, CAP / 128, NEXP), 256, GEMM_SMEM>>>(
        p_hcH, p_hcL, p_w2th, nullptr, nullptr, out, nullptr, b2, nullptr, nullptr, DFF, DD);
}

// round 15
// speedup vs baseline: 1.0801x; 1.0801x over previous
#include <cuda_runtime.h>
#include <cuda_bf16.h>
#include <math.h>
#include <stdint.h>

// Problem constants
#define BB    2
#define TT    1024
#define DD    1024
#define HH    16
#define DHH   64
#define NEXP  8
#define NTOK  2048          // B*T
#define DFF   4096
#define CAP   512           // NTOK*TOPK/NEXP

typedef __nv_bfloat16 bf16;

// ---------------- scratch (device globals: allocation-free) ----------------
__device__ __align__(128) bf16  g_hHi [NTOK * DD];
__device__ __align__(128) bf16  g_hLo [NTOK * DD];
__device__ __align__(128) float g_qkv [NTOK * 3 * DD];
__device__ __align__(128) bf16  g_aoHi[NTOK * DD];
__device__ __align__(128) bf16  g_aoLo[NTOK * DD];
__device__ __align__(128) float g_x2  [NTOK * DD];
__device__ __align__(128) float g_h2  [NTOK * DD];
__device__ __align__(128) bf16  g_h2Hi[NTOK * DD];
__device__ __align__(128) bf16  g_h2Lo[NTOK * DD];
__device__ int   g_tix  [NTOK * 2];
__device__ float g_tgate[NTOK * 2];
__device__ int   g_expert_tok [NEXP * CAP];    // zero-init
__device__ float g_expert_gate[NEXP * CAP];    // zero-init

// transposed split weights: [N][K] K-contiguous
__device__ __align__(128) bf16 g_wqkvTh[3 * DD * DD];
__device__ __align__(128) bf16 g_wqkvTl[3 * DD * DD];
__device__ __align__(128) bf16 g_wprojTh[DD * DD];
__device__ __align__(128) bf16 g_wprojTl[DD * DD];
__device__ __align__(128) bf16 g_w1th[NEXP * DFF * DD];   // hi only (2-term up)
__device__ __align__(128) bf16 g_w2th[NEXP * DD * DFF];   // hi only (2-term down)
// activations for MoE (hc split)
__device__ __align__(128) bf16 g_hcHi[NEXP * CAP * DFF];
__device__ __align__(128) bf16 g_hcLo[NEXP * CAP * DFF];

// ---------------- small helpers ----------------
__device__ __forceinline__ float warpReduceSum(float v) {
    v += __shfl_xor_sync(0xffffffffu, v, 16);
    v += __shfl_xor_sync(0xffffffffu, v, 8);
    v += __shfl_xor_sync(0xffffffffu, v, 4);
    v += __shfl_xor_sync(0xffffffffu, v, 2);
    v += __shfl_xor_sync(0xffffffffu, v, 1);
    return v;
}
__device__ __forceinline__ uint32_t smem_u32(const void* p) {
    uint32_t a;
    asm("{ .reg .u64 t; cvta.to.shared.u64 t, %1; cvt.u32.u64 %0, t; }" : "=r"(a) : "l"(p));
    return a;
}
__device__ __forceinline__ uint32_t swz(uint32_t o) { return o ^ ((o >> 3) & 0x70); }
__device__ __forceinline__ void cpa16(uint32_t s, const void* g) {
    asm volatile("cp.async.cg.shared.global [%0], [%1], 16;" :: "r"(s), "l"(g));
}
__device__ __forceinline__ uint4 ldsm4(uint32_t a) {
    uint4 r;
    asm volatile("ldmatrix.sync.aligned.m8n8.x4.shared.b16 {%0,%1,%2,%3}, [%4];"
                 : "=r"(r.x), "=r"(r.y), "=r"(r.z), "=r"(r.w) : "r"(a));
    return r;
}
__device__ __forceinline__ void mma16816(float* d, const uint4& a, uint32_t b0, uint32_t b1) {
    asm volatile(
        "mma.sync.aligned.m16n8k16.row.col.f32.bf16.bf16.f32 "
        "{%0,%1,%2,%3}, {%4,%5,%6,%7}, {%8,%9}, {%0,%1,%2,%3};"
        : "+f"(d[0]), "+f"(d[1]), "+f"(d[2]), "+f"(d[3])
        : "r"(a.x), "r"(a.y), "r"(a.z), "r"(a.w), "r"(b0), "r"(b1));
}
__device__ __forceinline__ void split2(float v, bf16& h, bf16& l) {
    h = __float2bfloat16(v);
    l = __float2bfloat16(v - __bfloat162float(h));
}
__device__ __forceinline__ uint32_t pack2bf(bf16 a, bf16 b) {
    return (uint32_t)__bfloat16_as_ushort(a) | ((uint32_t)__bfloat16_as_ushort(b) << 16);
}
__device__ __forceinline__ void sts64(uint32_t addr, uint32_t a, uint32_t b) {
    asm volatile("st.shared.v2.b32 [%0], {%1,%2};" :: "r"(addr), "r"(a), "r"(b));
}
__device__ __forceinline__ void sts16b(uint32_t addr, bf16 v) {
    asm volatile("st.shared.u16 [%0], %1;" :: "r"(addr), "h"((unsigned short)__bfloat16_as_ushort(v)));
}

// ---------------- LayerNorm (emits optional fp32 + split bf16) ----------------
__launch_bounds__(256)
__global__ void ln_kernel(const float* __restrict__ x,
                          const float* __restrict__ gamma,
                          const float* __restrict__ beta,
                          float* __restrict__ yf,
                          bf16* __restrict__ yh, bf16* __restrict__ yl)
{
    int row = blockIdx.x;
    int tid = threadIdx.x;
    int lane = tid & 31, wid = tid >> 5;
    const float* xr = x + (size_t)row * DD;
    __shared__ float red[8];

    float v[4];
#pragma unroll
    for (int i = 0; i < 4; i++) v[i] = xr[tid + i * 256];

    float s = v[0] + v[1] + v[2] + v[3];
    s = warpReduceSum(s);
    if (lane == 0) red[wid] = s;
    __syncthreads();
    float tot = red[0] + red[1] + red[2] + red[3] + red[4] + red[5] + red[6] + red[7];
    float mean = tot * (1.0f / 1024.0f);
    __syncthreads();

    float sq = 0.f;
#pragma unroll
    for (int i = 0; i < 4; i++) { float d = v[i] - mean; sq += d * d; }
    sq = warpReduceSum(sq);
    if (lane == 0) red[wid] = sq;
    __syncthreads();
    float vtot = red[0] + red[1] + red[2] + red[3] + red[4] + red[5] + red[6] + red[7];
    float rstd = rsqrtf(vtot * (1.0f / 1024.0f) + 1e-5f);

#pragma unroll
    for (int i = 0; i < 4; i++) {
        int d = tid + i * 256;
        float o = (v[i] - mean) * rstd * gamma[d] + beta[d];
        if (yf) yf[(size_t)row * DD + d] = o;
        bf16 h, l; split2(o, h, l);
        yh[(size_t)row * DD + d] = h;
        yl[(size_t)row * DD + d] = l;
    }
}

// ---------------- RoPE ----------------
__launch_bounds__(256)
__global__ void rope_kernel(float* __restrict__ qkv)
{
    int n = blockIdx.x;
    int t = n & (TT - 1);
    int tid = threadIdx.x;
    for (int i = tid; i < 1024; i += 256) {
        int s  = i >> 9;
        int hh = (i >> 5) & 15;
        int d  = i & 31;
        float inv = expf((float)d * -0.28782313662425576f);
        float ang = (float)t * inv;
        float sv, cv;
        sincosf(ang, &sv, &cv);
        size_t base = (size_t)n * (3 * DD) + (size_t)s * DD + hh * DHH;
        float a = qkv[base + d];
        float b = qkv[base + 32 + d];
        qkv[base + d]      = a * cv - b * sv;
        qkv[base + 32 + d] = b * cv + a * sv;
    }
}

// ---------------- Flash attention on tensor cores (split bf16, fp32 softmax) ----
#define ATT_SMEM 65536

__launch_bounds__(256, 2)
__global__ void attn_mma_kernel(const float* __restrict__ qkv,
                                bf16* __restrict__ aoH, bf16* __restrict__ aoL)
{
    extern __shared__ __align__(128) char dsm[];
    const uint32_t sb = smem_u32(dsm);
    const int tid = threadIdx.x, lane = tid & 31, wid = tid >> 5;
    const int qb = blockIdx.x, h = blockIdx.y, b = blockIdx.z;
    const int warp_m = wid * 16;

    for (int i = tid; i < 2048; i += 256) {
        int row = i >> 4, c4 = i & 15;
        const float4 v = *(const float4*)(qkv + (size_t)(b * TT + qb * 128 + row) * 3072
                                          + h * DHH + c4 * 4);
        bf16 h0, l0, h1, l1, h2, l2, h3, l3;
        split2(v.x, h0, l0); split2(v.y, h1, l1);
        split2(v.z, h2, l2); split2(v.w, h3, l3);
        uint32_t off = swz(row * 128 + c4 * 8);
        sts64(sb + off,         pack2bf(h0, h1), pack2bf(h2, h3));
        sts64(sb + 16384 + off, pack2bf(l0, l1), pack2bf(l2, l3));
    }

    float oc[8][4];
#pragma unroll
    for (int q = 0; q < 8; q++)
#pragma unroll
        for (int j = 0; j < 4; j++) oc[q][j] = 0.f;
    float m0 = -1e30f, m1 = -1e30f, l0s = 0.f, l1s = 0.f;

    const int r0g = qb * 128 + warp_m + (lane >> 2);
    const int r1g = r0g + 8;
    const int nkt = 2 * (qb + 1);

    for (int kt = 0; kt < nkt; kt++) {
        __syncthreads();
        for (int i = tid; i < 1024; i += 256) {
            int row = i >> 4, c4 = i & 15;
            size_t gbase = (size_t)(b * TT + kt * 64 + row) * 3072 + h * DHH + c4 * 4;
            const float4 kv = *(const float4*)(qkv + gbase + DD);
            bf16 h0, l0, h1, l1, h2, l2, h3, l3;
            split2(kv.x, h0, l0); split2(kv.y, h1, l1);
            split2(kv.z, h2, l2); split2(kv.w, h3, l3);
            uint32_t off = swz(row * 128 + c4 * 8);
            sts64(sb + 32768 + off, pack2bf(h0, h1), pack2bf(h2, h3));
            sts64(sb + 40960 + off, pack2bf(l0, l1), pack2bf(l2, l3));
            const float4 vv = *(const float4*)(qkv + gbase + 2 * DD);
#pragma unroll
            for (int j = 0; j < 4; j++) {
                float f = (&vv.x)[j];
                bf16 vh, vl; split2(f, vh, vl);
                uint32_t voff = swz((c4 * 4 + j) * 128 + row * 2);
                sts16b(sb + 49152 + voff, vh);
                sts16b(sb + 57344 + voff, vl);
            }
        }
        __syncthreads();

        float sc[8][4];
#pragma unroll
        for (int q = 0; q < 8; q++)
#pragma unroll
            for (int j = 0; j < 4; j++) sc[q][j] = 0.f;
#pragma unroll
        for (int k16 = 0; k16 < 4; k16++) {
            int kb = k16 * 32 + (lane >> 4) * 16;
            uint32_t aoff = swz((warp_m + (lane & 15)) * 128 + kb);
            uint4 Ah = ldsm4(sb + aoff);
            uint4 Al = ldsm4(sb + 16384 + aoff);
#pragma unroll
            for (int q = 0; q < 4; q++) {
                uint32_t boff = swz((q * 16 + (lane & 15)) * 128 + kb);
                uint4 Bh = ldsm4(sb + 32768 + boff);
                uint4 Bl = ldsm4(sb + 40960 + boff);
                mma16816(sc[2 * q],     Ah, Bh.x, Bh.z);
                mma16816(sc[2 * q + 1], Ah, Bh.y, Bh.w);
                mma16816(sc[2 * q],     Al, Bh.x, Bh.z);
                mma16816(sc[2 * q + 1], Al, Bh.y, Bh.w);
                mma16816(sc[2 * q],     Ah, Bl.x, Bl.z);
                mma16816(sc[2 * q + 1], Ah, Bl.y, Bl.w);
            }
        }

        const bool dmask = (64 * kt + 63 > qb * 128 + warp_m);
        float mt0 = -1e30f, mt1 = -1e30f;
#pragma unroll
        for (int q = 0; q < 8; q++) {
            int col = kt * 64 + q * 8 + 2 * (lane & 3);
            if (dmask) {
                sc[q][0] = (col     <= r0g) ? sc[q][0] * 0.125f : -1e30f;
                sc[q][1] = (col + 1 <= r0g) ? sc[q][1] * 0.125f : -1e30f;
                sc[q][2] = (col     <= r1g) ? sc[q][2] * 0.125f : -1e30f;
                sc[q][3] = (col + 1 <= r1g) ? sc[q][3] * 0.125f : -1e30f;
            } else {
                sc[q][0] *= 0.125f; sc[q][1] *= 0.125f;
                sc[q][2] *= 0.125f; sc[q][3] *= 0.125f;
            }
            mt0 = fmaxf(mt0, fmaxf(sc[q][0], sc[q][1]));
            mt1 = fmaxf(mt1, fmaxf(sc[q][2], sc[q][3]));
        }
        mt0 = fmaxf(mt0, __shfl_xor_sync(0xffffffffu, mt0, 1));
        mt0 = fmaxf(mt0, __shfl_xor_sync(0xffffffffu, mt0, 2));
        mt1 = fmaxf(mt1, __shfl_xor_sync(0xffffffffu, mt1, 1));
        mt1 = fmaxf(mt1, __shfl_xor_sync(0xffffffffu, mt1, 2));
        float mn0 = fmaxf(m0, mt0), mn1 = fmaxf(m1, mt1);
        float e0 = __expf(m0 - mn0), e1 = __expf(m1 - mn1);
        m0 = mn0; m1 = mn1;
        float ls0 = 0.f, ls1 = 0.f;
#pragma unroll
        for (int q = 0; q < 8; q++) {
            sc[q][0] = __expf(sc[q][0] - mn0); ls0 += sc[q][0];
            sc[q][1] = __expf(sc[q][1] - mn0); ls0 += sc[q][1];
            sc[q][2] = __expf(sc[q][2] - mn1); ls1 += sc[q][2];
            sc[q][3] = __expf(sc[q][3] - mn1); ls1 += sc[q][3];
        }
        ls0 += __shfl_xor_sync(0xffffffffu, ls0, 1);
        ls0 += __shfl_xor_sync(0xffffffffu, ls0, 2);
        ls1 += __shfl_xor_sync(0xffffffffu, ls1, 1);
        ls1 += __shfl_xor_sync(0xffffffffu, ls1, 2);
        l0s = l0s * e0 + ls0;
        l1s = l1s * e1 + ls1;
#pragma unroll
        for (int q = 0; q < 8; q++) {
            oc[q][0] *= e0; oc[q][1] *= e0;
            oc[q][2] *= e1; oc[q][3] *= e1;
        }

#pragma unroll
        for (int kk = 0; kk < 4; kk++) {
            bf16 ph[8], pl[8];
            split2(sc[2 * kk][0],     ph[0], pl[0]);
            split2(sc[2 * kk][1],     ph[1], pl[1]);
            split2(sc[2 * kk][2],     ph[2], pl[2]);
            split2(sc[2 * kk][3],     ph[3], pl[3]);
            split2(sc[2 * kk + 1][0], ph[4], pl[4]);
            split2(sc[2 * kk + 1][1], ph[5], pl[5]);
            split2(sc[2 * kk + 1][2], ph[6], pl[6]);
            split2(sc[2 * kk + 1][3], ph[7], pl[7]);
            uint4 Ah = make_uint4(pack2bf(ph[0], ph[1]), pack2bf(ph[2], ph[3]),
                                  pack2bf(ph[4], ph[5]), pack2bf(ph[6], ph[7]));
            uint4 Al = make_uint4(pack2bf(pl[0], pl[1]), pack2bf(pl[2], pl[3]),
                                  pack2bf(pl[4], pl[5]), pack2bf(pl[6], pl[7]));
            int kb = kk * 32 + (lane >> 4) * 16;
#pragma unroll
            for (int q = 0; q < 4; q++) {
                uint32_t boff = swz((q * 16 + (lane & 15)) * 128 + kb);
                uint4 Vh = ldsm4(sb + 49152 + boff);
                uint4 Vl = ldsm4(sb + 57344 + boff);
                mma16816(oc[2 * q],     Ah, Vh.x, Vh.z);
                mma16816(oc[2 * q + 1], Ah, Vh.y, Vh.w);
                mma16816(oc[2 * q],     Al, Vh.x, Vh.z);
                mma16816(oc[2 * q + 1], Al, Vh.y, Vh.w);
                mma16816(oc[2 * q],     Ah, Vl.x, Vl.z);
                mma16816(oc[2 * q + 1], Ah, Vl.y, Vl.w);
            }
        }
    }

    float inv0 = 1.0f / l0s, inv1 = 1.0f / l1s;
    int tok0 = b * TT + qb * 128 + warp_m + (lane >> 2);
#pragma unroll
    for (int q = 0; q < 8; q++) {
        int c = h * DHH + q * 8 + 2 * (lane & 3);
        bf16 h0, l0, h1, l1;
        split2(oc[q][0] * inv0, h0, l0);
        split2(oc[q][1] * inv0, h1, l1);
        *(uint32_t*)&aoH[(size_t)tok0 * DD + c] = pack2bf(h0, h1);
        *(uint32_t*)&aoL[(size_t)tok0 * DD + c] = pack2bf(l0, l1);
        split2(oc[q][2] * inv1, h0, l0);
        split2(oc[q][3] * inv1, h1, l1);
        *(uint32_t*)&aoH[(size_t)(tok0 + 8) * DD + c] = pack2bf(h0, h1);
        *(uint32_t*)&aoL[(size_t)(tok0 + 8) * DD + c] = pack2bf(l0, l1);
    }
}

// ---------------- Router ----------------
__launch_bounds__(256)
__global__ void router_kernel(const float* __restrict__ h2,
                              const float* __restrict__ noise,
                              const float* __restrict__ w_rl,
                              const float* __restrict__ b_rl,
                              const float* __restrict__ w_rn,
                              const float* __restrict__ b_rn)
{
    int n = blockIdx.x;
    int tid = threadIdx.x;
    int lane = tid & 31, wid = tid >> 5;
    const float* hr = h2 + (size_t)n * DD;

    float aL[8], aN[8];
#pragma unroll
    for (int e = 0; e < 8; e++) { aL[e] = 0.f; aN[e] = 0.f; }

    for (int d = tid; d < DD; d += 256) {
        float hv = hr[d];
        const float4* rl4 = (const float4*)(w_rl + (size_t)d * 8);
        const float4* rn4 = (const float4*)(w_rn + (size_t)d * 8);
        float4 l0 = rl4[0], l1 = rl4[1];
        float4 n0 = rn4[0], n1 = rn4[1];
        aL[0] += hv * l0.x; aL[1] += hv * l0.y; aL[2] += hv * l0.z; aL[3] += hv * l0.w;
        aL[4] += hv * l1.x; aL[5] += hv * l1.y; aL[6] += hv * l1.z; aL[7] += hv * l1.w;
        aN[0] += hv * n0.x; aN[1] += hv * n0.y; aN[2] += hv * n0.z; aN[3] += hv * n0.w;
        aN[4] += hv * n1.x; aN[5] += hv * n1.y; aN[6] += hv * n1.z; aN[7] += hv * n1.w;
    }
#pragma unroll
    for (int e = 0; e < 8; e++) { aL[e] = warpReduceSum(aL[e]); aN[e] = warpReduceSum(aN[e]); }

    __shared__ float sL[8][8], sN[8][8];
    if (lane == 0) {
#pragma unroll
        for (int e = 0; e < 8; e++) { sL[wid][e] = aL[e]; sN[wid][e] = aN[e]; }
    }
    __syncthreads();

    if (tid == 0) {
        float v0 = -1e38f, v1 = -1e38f;
        int i0 = 0, i1 = 0;
#pragma unroll
        for (int e = 0; e < 8; e++) {
            float L = 0.f, Nn = 0.f;
#pragma unroll
            for (int w = 0; w < 8; w++) { L += sL[w][e]; Nn += sN[w][e]; }
            float spin = Nn + b_rn[e];
            float sp = fmaxf(spin, 0.f) + log1pf(expf(-fabsf(spin)));
            float v = L + b_rl[e] + noise[(size_t)n * 8 + e] * sp;
            if (v > v0)      { v1 = v0; i1 = i0; v0 = v; i0 = e; }
            else if (v > v1) { v1 = v;  i1 = e; }
        }
        float ex = expf(v1 - v0);
        float inv = 1.0f / (1.0f + ex);
        g_tix[n * 2]     = i0;
        g_tix[n * 2 + 1] = i1;
        g_tgate[n * 2]     = inv;
        g_tgate[n * 2 + 1] = ex * inv;
    }
}

// ---------------- Expert assignment ----------------
__launch_bounds__(256)
__global__ void assign_kernel()
{
    int e = blockIdx.x;
    int tid = threadIdx.x;
    int lane = tid & 31, wid = tid >> 5;
    __shared__ int warpsum[8];

    int flags[8];
    int cnt = 0;
#pragma unroll
    for (int i = 0; i < 8; i++) {
        int tok = tid * 8 + i;
        int f = 0;
        if (g_tix[tok * 2] == e) f = 1;
        else if (g_tix[tok * 2 + 1] == e) f = 2;
        flags[i] = f;
        cnt += (f != 0);
    }
    int incl = cnt;
#pragma unroll
    for (int off = 1; off < 32; off <<= 1) {
        int v = __shfl_up_sync(0xffffffffu, incl, off);
        if (lane >= off) incl += v;
    }
    if (lane == 31) warpsum[wid] = incl;
    __syncthreads();
    int wbase = 0;
    for (int w = 0; w < wid; w++) wbase += warpsum[w];
    int base = wbase + incl - cnt;

#pragma unroll
    for (int i = 0; i < 8; i++) {
        if (flags[i]) {
            if (base < CAP) {
                int tok = tid * 8 + i;
                g_expert_tok[e * CAP + base]  = tok;
                g_expert_gate[e * CAP + base] = g_tgate[tok * 2 + (flags[i] - 1)];
            }
            base++;
        }
    }
}

// ---------------- weight transpose + split (vectorized 4B stores) ----------------
// W [e][K][N] fp32 -> Oh (and optionally Ol) [e][N][K] bf16
__global__ void conv_w_kernel(const float* __restrict__ W,
                              bf16* __restrict__ Oh, bf16* __restrict__ Ol,
                              int K, int N)
{
    __shared__ float tile[32][33];
    int e = blockIdx.z;
    const float* Wp = W + (size_t)e * K * N;
    size_t ob = (size_t)e * K * N;
    int n0 = blockIdx.x * 32, k0 = blockIdx.y * 32;
    int tx = threadIdx.x, ty = threadIdx.y;   // 32 x 8
#pragma unroll
    for (int i = 0; i < 32; i += 8)
        tile[ty + i][tx] = Wp[(size_t)(k0 + ty + i) * N + n0 + tx];
    __syncthreads();
    int tid = ty * 32 + tx;
    int kp = tid & 15;
    int nl0 = tid >> 4;
#pragma unroll
    for (int it = 0; it < 2; it++) {
        int nl = nl0 + it * 16;
        float v0 = tile[2 * kp][nl];
        float v1 = tile[2 * kp + 1][nl];
        bf16 h0, l0, h1, l1;
        split2(v0, h0, l0);
        split2(v1, h1, l1);
        size_t o = ob + (size_t)(n0 + nl) * K + k0 + 2 * kp;
        *(uint32_t*)&Oh[o] = pack2bf(h0, h1);
        if (Ol) *(uint32_t*)&Ol[o] = pack2bf(l0, l1);
    }
}

// ---------------- split-bf16 tensor-core GEMM (proven structure) ----------------
// C[M][N] = A[M][K] @ B[N][K]^T.  K-chunk 64, double-buffered, 128B-row SW128.
// S3=1: 3-term split, stage 64KB (Ah|Al|Bh|Bl), occupancy 1.
// S3=0: 2-term split, stage compacted to 48KB (Ah|Al|Bh), occupancy 2.
// MODE 0: C = A@B                                (qkv)
// MODE 1: C = C2 = X + A@B                       (attn proj + residual)
// MODE 2: hc = relu(gather(A)@B + b1[e])         (expert up; A rows via g_expert_tok)
// MODE 3: out[tok] += (A@B + b2[e]) * gate       (expert down, atomic scatter)
#define GEMM_SMEM_S3  (2 * 65536)
#define GEMM_SMEM_S2  (2 * 49152)

template<bool S3>
__device__ __forceinline__ void compute_stage(uint32_t sb, int warp_m, int warp_n,
                                              int lane, float acc[2][8][4])
{
    int lr = lane & 15, lc = lane >> 4;
#pragma unroll
    for (int k16 = 0; k16 < 4; k16++) {
        int kb = k16 * 32 + lc * 16;
        uint32_t a0o = swz((warp_m + lr) * 128 + kb);
        uint32_t a1o = swz((warp_m + 16 + lr) * 128 + kb);
        uint4 Ah0 = ldsm4(sb + a0o);
        uint4 Ah1 = ldsm4(sb + a1o);
        uint4 Al0 = ldsm4(sb + 16384 + a0o);
        uint4 Al1 = ldsm4(sb + 16384 + a1o);
#pragma unroll
        for (int q = 0; q < 4; q++) {
            uint32_t off = swz((warp_n + q * 16 + lr) * 128 + kb);
            uint4 Bh = ldsm4(sb + 32768 + off);
            mma16816(acc[0][q * 2 + 0], Ah0, Bh.x, Bh.z);
            mma16816(acc[0][q * 2 + 1], Ah0, Bh.y, Bh.w);
            mma16816(acc[1][q * 2 + 0], Ah1, Bh.x, Bh.z);
            mma16816(acc[1][q * 2 + 1], Ah1, Bh.y, Bh.w);
            mma16816(acc[0][q * 2 + 0], Al0, Bh.x, Bh.z);
            mma16816(acc[0][q * 2 + 1], Al0, Bh.y, Bh.w);
            mma16816(acc[1][q * 2 + 0], Al1, Bh.x, Bh.z);
            mma16816(acc[1][q * 2 + 1], Al1, Bh.y, Bh.w);
            if (S3) {
                uint4 Bl = ldsm4(sb + 49152 + off);
                mma16816(acc[0][q * 2 + 0], Ah0, Bl.x, Bl.z);
                mma16816(acc[0][q * 2 + 1], Ah0, Bl.y, Bl.w);
                mma16816(acc[1][q * 2 + 0], Ah1, Bl.x, Bl.z);
                mma16816(acc[1][q * 2 + 1], Ah1, Bl.y, Bl.w);
            }
        }
    }
}

template<int MODE, bool S3>
__launch_bounds__(256, S3 ? 1 : 2)
__global__ void gemm_bf16(const bf16* __restrict__ Ah, const bf16* __restrict__ Al,
                          const bf16* __restrict__ Bh, const bf16* __restrict__ Bl,
                          float* __restrict__ C, float* __restrict__ C2,
                          const float* __restrict__ Xres,
                          const float* __restrict__ bias,
                          bf16* __restrict__ Oh, bf16* __restrict__ Ol,
                          int K, int N)
{
    constexpr uint32_t STAGE = S3 ? 65536u : 49152u;
    extern __shared__ __align__(128) char dsm[];
    const uint32_t sb0 = smem_u32(dsm);
    const int tid = threadIdx.x, lane = tid & 31, wid = tid >> 5;
    const int e = blockIdx.z;
    const int m0 = blockIdx.y * 128, n0 = blockIdx.x * 128;
    const int warp_m = (wid >> 1) * 32, warp_n = (wid & 1) * 64;

    const size_t rK = (size_t)K * 2;   // bytes per row
    const char* pAh;
    const char* pAl;
    if (MODE == 2) { pAh = (const char*)Ah; pAl = (const char*)Al; }  // token-indirect rows
    else if (MODE == 3) {
        pAh = (const char*)(Ah + ((size_t)e * CAP + m0) * K);
        pAl = (const char*)(Al + ((size_t)e * CAP + m0) * K);
    } else {
        pAh = (const char*)(Ah + (size_t)m0 * K);
        pAl = (const char*)(Al + (size_t)m0 * K);
    }
    const char* pBh = (const char*)(Bh + ((MODE >= 2) ? (size_t)e * N * K : 0) + (size_t)n0 * K);
    const char* pBl = (const char*)(S3 ? (Bl + ((MODE >= 2) ? (size_t)e * N * K : 0) + (size_t)n0 * K) : nullptr);
    const int NC = K >> 6;

    auto issue = [&](int c) {
        uint32_t sbuf = sb0 + (c & 1) * STAGE;
        int kb = c * 128;
#pragma unroll
        for (int i = 0; i < 4; i++) {
            int idx = tid + i * 256;
            int row = idx >> 3;
            int c16 = (idx & 7) * 16;
            uint32_t sw = swz(row * 128 + c16);
            size_t goA;
            if (MODE == 2) {
                int tok = g_expert_tok[e * CAP + m0 + row];
                goA = (size_t)tok * rK + kb + c16;
            } else {
                goA = (size_t)row * rK + kb + c16;
            }
            size_t goB = (size_t)row * rK + kb + c16;
            cpa16(sbuf + sw,         pAh + goA);
            cpa16(sbuf + 16384 + sw, pAl + goA);
            cpa16(sbuf + 32768 + sw, pBh + goB);
            if (S3) cpa16(sbuf + 49152 + sw, pBl + goB);
        }
        asm volatile("cp.async.commit_group;" ::: "memory");
    };

    float acc[2][8][4];
#pragma unroll
    for (int a = 0; a < 2; a++)
#pragma unroll
        for (int b = 0; b < 8; b++)
#pragma unroll
            for (int c = 0; c < 4; c++) acc[a][b][c] = 0.f;

    issue(0);
    for (int c = 0; c < NC; c++) {
        if (c + 1 < NC) {
            issue(c + 1);
            asm volatile("cp.async.wait_group 1;" ::: "memory");
        } else {
            asm volatile("cp.async.wait_group 0;" ::: "memory");
        }
        __syncthreads();
        compute_stage<S3>(sb0 + (c & 1) * STAGE, warp_m, warp_n, lane, acc);
        __syncthreads();
    }

    // epilogue
#pragma unroll
    for (int mt = 0; mt < 2; mt++) {
#pragma unroll
        for (int rh = 0; rh < 2; rh++) {
            int gr = m0 + warp_m + mt * 16 + rh * 8 + (lane >> 2);
            int tok = 0; float gt = 0.f;
            if (MODE == 3) {
                int slot = e * CAP + gr;
                tok = g_expert_tok[slot];
                gt = g_expert_gate[slot];
            }
#pragma unroll
            for (int nt = 0; nt < 8; nt++) {
                int gc = n0 + warp_n + nt * 8 + (lane & 3) * 2;
                float d0 = acc[mt][nt][rh * 2 + 0];
                float d1 = acc[mt][nt][rh * 2 + 1];
                if (MODE == 0) {
                    *(float2*)&C[(size_t)gr * N + gc] = make_float2(d0, d1);
                } else if (MODE == 1) {
                    size_t ix = (size_t)gr * N + gc;
                    float2 xv = *(const float2*)&Xres[ix];
                    float2 v = make_float2(d0 + xv.x, d1 + xv.y);
                    *(float2*)&C[ix] = v;
                    *(float2*)&C2[ix] = v;
                } else if (MODE == 2) {
                    float v0 = fmaxf(d0 + bias[(size_t)e * N + gc], 0.f);
                    float v1 = fmaxf(d1 + bias[(size_t)e * N + gc + 1], 0.f);
                    bf16 h0, l0, h1, l1;
                    split2(v0, h0, l0);
                    split2(v1, h1, l1);
                    size_t ix = ((size_t)e * CAP + gr) * (size_t)N + gc;
                    *(uint32_t*)&Oh[ix] = pack2bf(h0, h1);
                    *(uint32_t*)&Ol[ix] = pack2bf(l0, l1);
                } else {
                    if (gt != 0.f) {
                        float v0 = (d0 + bias[(size_t)e * N + gc]) * gt;
                        float v1 = (d1 + bias[(size_t)e * N + gc + 1]) * gt;
                        atomicAdd(&C2[(size_t)tok * DD + gc], v0);
                        atomicAdd(&C2[(size_t)tok * DD + gc + 1], v1);
                    }
                }
            }
        }
    }
}

// ---------------- launch ----------------
extern "C" void kernel_launch(void* const* d_in, const int* in_sizes, int n_in,
                              void* d_out, int out_size)
{
    const float* x      = (const float*)d_in[0];
    const float* noise  = (const float*)d_in[1];
    const float* ln1_g  = (const float*)d_in[2];
    const float* ln1_b  = (const float*)d_in[3];
    const float* ln2_g  = (const float*)d_in[4];
    const float* ln2_b  = (const float*)d_in[5];
    const float* w_qkv  = (const float*)d_in[6];
    const float* w_proj = (const float*)d_in[7];
    const float* w_rl   = (const float*)d_in[8];
    const float* b_rl   = (const float*)d_in[9];
    const float* w_rn   = (const float*)d_in[10];
    const float* b_rn   = (const float*)d_in[11];
    const float* w1     = (const float*)d_in[12];
    const float* b1     = (const float*)d_in[13];
    const float* w2     = (const float*)d_in[14];
    const float* b2     = (const float*)d_in[15];
    float* out = (float*)d_out;

    float *p_qkv, *p_x2, *p_h2;
    bf16 *p_hH, *p_hL, *p_aoH, *p_aoL, *p_h2H, *p_h2L;
    bf16 *p_wqkvTh, *p_wqkvTl, *p_wprojTh, *p_wprojTl;
    bf16 *p_w1th, *p_w2th;
    bf16 *p_hcH, *p_hcL;
    cudaGetSymbolAddress((void**)&p_qkv, g_qkv);
    cudaGetSymbolAddress((void**)&p_x2,  g_x2);
    cudaGetSymbolAddress((void**)&p_h2,  g_h2);
    cudaGetSymbolAddress((void**)&p_hH,  g_hHi);
    cudaGetSymbolAddress((void**)&p_hL,  g_hLo);
    cudaGetSymbolAddress((void**)&p_aoH, g_aoHi);
    cudaGetSymbolAddress((void**)&p_aoL, g_aoLo);
    cudaGetSymbolAddress((void**)&p_h2H, g_h2Hi);
    cudaGetSymbolAddress((void**)&p_h2L, g_h2Lo);
    cudaGetSymbolAddress((void**)&p_wqkvTh, g_wqkvTh);
    cudaGetSymbolAddress((void**)&p_wqkvTl, g_wqkvTl);
    cudaGetSymbolAddress((void**)&p_wprojTh, g_wprojTh);
    cudaGetSymbolAddress((void**)&p_wprojTl, g_wprojTl);
    cudaGetSymbolAddress((void**)&p_w1th, g_w1th);
    cudaGetSymbolAddress((void**)&p_w2th, g_w2th);
    cudaGetSymbolAddress((void**)&p_hcH, g_hcHi);
    cudaGetSymbolAddress((void**)&p_hcL, g_hcLo);

    cudaFuncSetAttribute((const void*)gemm_bf16<0, true>,  cudaFuncAttributeMaxDynamicSharedMemorySize, GEMM_SMEM_S3);
    cudaFuncSetAttribute((const void*)gemm_bf16<1, true>,  cudaFuncAttributeMaxDynamicSharedMemorySize, GEMM_SMEM_S3);
    cudaFuncSetAttribute((const void*)gemm_bf16<2, false>, cudaFuncAttributeMaxDynamicSharedMemorySize, GEMM_SMEM_S2);
    cudaFuncSetAttribute((const void*)gemm_bf16<3, false>, cudaFuncAttributeMaxDynamicSharedMemorySize, GEMM_SMEM_S2);
    cudaFuncSetAttribute(attn_mma_kernel, cudaFuncAttributeMaxDynamicSharedMemorySize, ATT_SMEM);

    // weight transpose + split (MoE weights: hi only — 2-term GEMMs)
    conv_w_kernel<<<dim3(3 * DD / 32, DD / 32, 1), dim3(32, 8)>>>(w_qkv, p_wqkvTh, p_wqkvTl, DD, 3 * DD);
    conv_w_kernel<<<dim3(DD / 32, DD / 32, 1), dim3(32, 8)>>>(w_proj, p_wprojTh, p_wprojTl, DD, DD);
    conv_w_kernel<<<dim3(DFF / 32, DD / 32, NEXP), dim3(32, 8)>>>(w1, p_w1th, nullptr, DD, DFF);
    conv_w_kernel<<<dim3(DD / 32, DFF / 32, NEXP), dim3(32, 8)>>>(w2, p_w2th, nullptr, DFF, DD);

    // 1. h = LN1(x)  (split only)
    ln_kernel<<<NTOK, 256>>>(x, ln1_g, ln1_b, nullptr, p_hH, p_hL);
    // 2. qkv = h @ w_qkv   [tensor, 3-term, occ1]
    gemm_bf16<0, true><<<dim3(24, 16, 1), 256, GEMM_SMEM_S3>>>(p_hH, p_hL, p_wqkvTh, p_wqkvTl,
                                                               p_qkv, nullptr, nullptr, nullptr,
                                                               nullptr, nullptr, DD, 3 * DD);
    // 3. RoPE
    rope_kernel<<<NTOK, 256>>>(p_qkv);
    // 4. attention [tensor, 3-term]  (128-query tiles -> grid.x = TT/128 = 8)
    attn_mma_kernel<<<dim3(8, HH, BB), 256, ATT_SMEM>>>(p_qkv, p_aoH, p_aoL);
    // 5. x2 = x + ao @ w_proj  (seeds out)   [tensor, 3-term, occ1]
    gemm_bf16<1, true><<<dim3(8, 16, 1), 256, GEMM_SMEM_S3>>>(p_aoH, p_aoL, p_wprojTh, p_wprojTl,
                                                              p_x2, out, x, nullptr,
                                                              nullptr, nullptr, DD, DD);
    // 6. h2 = LN2(x2)  (fp32 + split)
    ln_kernel<<<NTOK, 256>>>(p_x2, ln2_g, ln2_b, p_h2, p_h2H, p_h2L);
    // 7. router
    router_kernel<<<NTOK, 256>>>(p_h2, noise, w_rl, b_rl, w_rn, b_rn);
    // 8. capacity assignment
    assign_kernel<<<NEXP, 256>>>();
    // 9. expert up (gather fused): hc = relu(h2[tok] @ w1 + b1)   [tensor, 2-term, occ2]
    gemm_bf16<2, false><<<dim3(DFF / 128, CAP / 128, NEXP), 256, GEMM_SMEM_S2>>>(
        p_h2H, p_h2L, p_w1th, nullptr, nullptr, nullptr, nullptr, b1, p_hcH, p_hcL, DD, DFF);
    // 10. expert down: out += (hc @ w2 + b2) * gate   [tensor, 2-term, occ2]
    gemm_bf16<3, false><<<dim3(DD / 128, CAP / 128, NEXP), 256, GEMM_SMEM_S2>>>(
        p_hcH, p_hcL, p_w2th, nullptr, nullptr, out, nullptr, b2, nullptr, nullptr, DFF, DD);
}

// round 17
// speedup vs baseline: 1.1069x; 1.0249x over previous
#include <cuda_runtime.h>
#include <cuda_bf16.h>
#include <math.h>
#include <stdint.h>

// Problem constants
#define BB    2
#define TT    1024
#define DD    1024
#define HH    16
#define DHH   64
#define NEXP  8
#define NTOK  2048          // B*T
#define DFF   4096
#define CAP   512           // NTOK*TOPK/NEXP

typedef __nv_bfloat16 bf16;

// ---------------- scratch (device globals: allocation-free) ----------------
__device__ __align__(128) bf16  g_hHi [NTOK * DD];
__device__ __align__(128) bf16  g_hLo [NTOK * DD];
__device__ __align__(128) float g_qkv [NTOK * 3 * DD];
__device__ __align__(128) bf16  g_aoHi[NTOK * DD];
__device__ __align__(128) bf16  g_aoLo[NTOK * DD];
__device__ __align__(128) float g_x2  [NTOK * DD];
__device__ __align__(128) float g_h2  [NTOK * DD];
__device__ __align__(128) bf16  g_h2Hi[NTOK * DD];
__device__ __align__(128) bf16  g_h2Lo[NTOK * DD];
__device__ int   g_tix  [NTOK * 2];
__device__ float g_tgate[NTOK * 2];
__device__ int   g_expert_tok [NEXP * CAP];    // zero-init
__device__ float g_expert_gate[NEXP * CAP];    // zero-init

// transposed split weights: [N][K] K-contiguous
__device__ __align__(128) bf16 g_wqkvTh[3 * DD * DD];
__device__ __align__(128) bf16 g_wqkvTl[3 * DD * DD];
__device__ __align__(128) bf16 g_wprojTh[DD * DD];
__device__ __align__(128) bf16 g_wprojTl[DD * DD];
__device__ __align__(128) bf16 g_w1th[NEXP * DFF * DD];   // hi only (2-term up)
__device__ __align__(128) bf16 g_w2th[NEXP * DD * DFF];   // hi only (2-term down)
// activations for MoE (hc split)
__device__ __align__(128) bf16 g_hcHi[NEXP * CAP * DFF];
__device__ __align__(128) bf16 g_hcLo[NEXP * CAP * DFF];

// ---------------- small helpers ----------------
__device__ __forceinline__ float warpReduceSum(float v) {
    v += __shfl_xor_sync(0xffffffffu, v, 16);
    v += __shfl_xor_sync(0xffffffffu, v, 8);
    v += __shfl_xor_sync(0xffffffffu, v, 4);
    v += __shfl_xor_sync(0xffffffffu, v, 2);
    v += __shfl_xor_sync(0xffffffffu, v, 1);
    return v;
}
__device__ __forceinline__ uint32_t smem_u32(const void* p) {
    uint32_t a;
    asm("{ .reg .u64 t; cvta.to.shared.u64 t, %1; cvt.u32.u64 %0, t; }" : "=r"(a) : "l"(p));
    return a;
}
__device__ __forceinline__ uint32_t swz(uint32_t o) { return o ^ ((o >> 3) & 0x70); }
__device__ __forceinline__ void cpa16(uint32_t s, const void* g) {
    asm volatile("cp.async.cg.shared.global [%0], [%1], 16;" :: "r"(s), "l"(g));
}
__device__ __forceinline__ uint4 ldsm4(uint32_t a) {
    uint4 r;
    asm volatile("ldmatrix.sync.aligned.m8n8.x4.shared.b16 {%0,%1,%2,%3}, [%4];"
                 : "=r"(r.x), "=r"(r.y), "=r"(r.z), "=r"(r.w) : "r"(a));
    return r;
}
__device__ __forceinline__ void mma16816(float* d, const uint4& a, uint32_t b0, uint32_t b1) {
    asm volatile(
        "mma.sync.aligned.m16n8k16.row.col.f32.bf16.bf16.f32 "
        "{%0,%1,%2,%3}, {%4,%5,%6,%7}, {%8,%9}, {%0,%1,%2,%3};"
        : "+f"(d[0]), "+f"(d[1]), "+f"(d[2]), "+f"(d[3])
        : "r"(a.x), "r"(a.y), "r"(a.z), "r"(a.w), "r"(b0), "r"(b1));
}
__device__ __forceinline__ void split2(float v, bf16& h, bf16& l) {
    h = __float2bfloat16(v);
    l = __float2bfloat16(v - __bfloat162float(h));
}
__device__ __forceinline__ uint32_t pack2bf(bf16 a, bf16 b) {
    return (uint32_t)__bfloat16_as_ushort(a) | ((uint32_t)__bfloat16_as_ushort(b) << 16);
}
__device__ __forceinline__ void sts64(uint32_t addr, uint32_t a, uint32_t b) {
    asm volatile("st.shared.v2.b32 [%0], {%1,%2};" :: "r"(addr), "r"(a), "r"(b));
}
__device__ __forceinline__ void sts16b(uint32_t addr, bf16 v) {
    asm volatile("st.shared.u16 [%0], %1;" :: "r"(addr), "h"((unsigned short)__bfloat16_as_ushort(v)));
}

// ---------------- LayerNorm (emits optional fp32 + split bf16) ----------------
__launch_bounds__(256)
__global__ void ln_kernel(const float* __restrict__ x,
                          const float* __restrict__ gamma,
                          const float* __restrict__ beta,
                          float* __restrict__ yf,
                          bf16* __restrict__ yh, bf16* __restrict__ yl)
{
    int row = blockIdx.x;
    int tid = threadIdx.x;
    int lane = tid & 31, wid = tid >> 5;
    const float* xr = x + (size_t)row * DD;
    __shared__ float red[8];

    float v[4];
#pragma unroll
    for (int i = 0; i < 4; i++) v[i] = xr[tid + i * 256];

    float s = v[0] + v[1] + v[2] + v[3];
    s = warpReduceSum(s);
    if (lane == 0) red[wid] = s;
    __syncthreads();
    float tot = red[0] + red[1] + red[2] + red[3] + red[4] + red[5] + red[6] + red[7];
    float mean = tot * (1.0f / 1024.0f);
    __syncthreads();

    float sq = 0.f;
#pragma unroll
    for (int i = 0; i < 4; i++) { float d = v[i] - mean; sq += d * d; }
    sq = warpReduceSum(sq);
    if (lane == 0) red[wid] = sq;
    __syncthreads();
    float vtot = red[0] + red[1] + red[2] + red[3] + red[4] + red[5] + red[6] + red[7];
    float rstd = rsqrtf(vtot * (1.0f / 1024.0f) + 1e-5f);

#pragma unroll
    for (int i = 0; i < 4; i++) {
        int d = tid + i * 256;
        float o = (v[i] - mean) * rstd * gamma[d] + beta[d];
        if (yf) yf[(size_t)row * DD + d] = o;
        bf16 h, l; split2(o, h, l);
        yh[(size_t)row * DD + d] = h;
        yl[(size_t)row * DD + d] = l;
    }
}

// ---------------- RoPE ----------------
__launch_bounds__(256)
__global__ void rope_kernel(float* __restrict__ qkv)
{
    int n = blockIdx.x;
    int t = n & (TT - 1);
    int tid = threadIdx.x;
    for (int i = tid; i < 1024; i += 256) {
        int s  = i >> 9;
        int hh = (i >> 5) & 15;
        int d  = i & 31;
        float inv = expf((float)d * -0.28782313662425576f);
        float ang = (float)t * inv;
        float sv, cv;
        sincosf(ang, &sv, &cv);
        size_t base = (size_t)n * (3 * DD) + (size_t)s * DD + hh * DHH;
        float a = qkv[base + d];
        float b = qkv[base + 32 + d];
        qkv[base + d]      = a * cv - b * sv;
        qkv[base + 32 + d] = b * cv + a * sv;
    }
}

// ---------------- Flash attention on tensor cores (split bf16, fp32 softmax) ----
#define ATT_SMEM 65536

__launch_bounds__(256, 2)
__global__ void attn_mma_kernel(const float* __restrict__ qkv,
                                bf16* __restrict__ aoH, bf16* __restrict__ aoL)
{
    extern __shared__ __align__(128) char dsm[];
    const uint32_t sb = smem_u32(dsm);
    const int tid = threadIdx.x, lane = tid & 31, wid = tid >> 5;
    const int qb = blockIdx.x, h = blockIdx.y, b = blockIdx.z;
    const int warp_m = wid * 16;

    for (int i = tid; i < 2048; i += 256) {
        int row = i >> 4, c4 = i & 15;
        const float4 v = *(const float4*)(qkv + (size_t)(b * TT + qb * 128 + row) * 3072
                                          + h * DHH + c4 * 4);
        bf16 h0, l0, h1, l1, h2, l2, h3, l3;
        split2(v.x, h0, l0); split2(v.y, h1, l1);
        split2(v.z, h2, l2); split2(v.w, h3, l3);
        uint32_t off = swz(row * 128 + c4 * 8);
        sts64(sb + off,         pack2bf(h0, h1), pack2bf(h2, h3));
        sts64(sb + 16384 + off, pack2bf(l0, l1), pack2bf(l2, l3));
    }

    float oc[8][4];
#pragma unroll
    for (int q = 0; q < 8; q++)
#pragma unroll
        for (int j = 0; j < 4; j++) oc[q][j] = 0.f;
    float m0 = -1e30f, m1 = -1e30f, l0s = 0.f, l1s = 0.f;

    const int r0g = qb * 128 + warp_m + (lane >> 2);
    const int r1g = r0g + 8;
    const int nkt = 2 * (qb + 1);

    for (int kt = 0; kt < nkt; kt++) {
        __syncthreads();
        for (int i = tid; i < 1024; i += 256) {
            int row = i >> 4, c4 = i & 15;
            size_t gbase = (size_t)(b * TT + kt * 64 + row) * 3072 + h * DHH + c4 * 4;
            const float4 kv = *(const float4*)(qkv + gbase + DD);
            bf16 h0, l0, h1, l1, h2, l2, h3, l3;
            split2(kv.x, h0, l0); split2(kv.y, h1, l1);
            split2(kv.z, h2, l2); split2(kv.w, h3, l3);
            uint32_t off = swz(row * 128 + c4 * 8);
            sts64(sb + 32768 + off, pack2bf(h0, h1), pack2bf(h2, h3));
            sts64(sb + 40960 + off, pack2bf(l0, l1), pack2bf(l2, l3));
            const float4 vv = *(const float4*)(qkv + gbase + 2 * DD);
#pragma unroll
            for (int j = 0; j < 4; j++) {
                float f = (&vv.x)[j];
                bf16 vh, vl; split2(f, vh, vl);
                uint32_t voff = swz((c4 * 4 + j) * 128 + row * 2);
                sts16b(sb + 49152 + voff, vh);
                sts16b(sb + 57344 + voff, vl);
            }
        }
        __syncthreads();

        float sc[8][4];
#pragma unroll
        for (int q = 0; q < 8; q++)
#pragma unroll
            for (int j = 0; j < 4; j++) sc[q][j] = 0.f;
#pragma unroll
        for (int k16 = 0; k16 < 4; k16++) {
            int kb = k16 * 32 + (lane >> 4) * 16;
            uint32_t aoff = swz((warp_m + (lane & 15)) * 128 + kb);
            uint4 Ah = ldsm4(sb + aoff);
            uint4 Al = ldsm4(sb + 16384 + aoff);
#pragma unroll
            for (int q = 0; q < 4; q++) {
                uint32_t boff = swz((q * 16 + (lane & 15)) * 128 + kb);
                uint4 Bh = ldsm4(sb + 32768 + boff);
                uint4 Bl = ldsm4(sb + 40960 + boff);
                mma16816(sc[2 * q],     Ah, Bh.x, Bh.z);
                mma16816(sc[2 * q + 1], Ah, Bh.y, Bh.w);
                mma16816(sc[2 * q],     Al, Bh.x, Bh.z);
                mma16816(sc[2 * q + 1], Al, Bh.y, Bh.w);
                mma16816(sc[2 * q],     Ah, Bl.x, Bl.z);
                mma16816(sc[2 * q + 1], Ah, Bl.y, Bl.w);
            }
        }

        const bool dmask = (64 * kt + 63 > qb * 128 + warp_m);
        float mt0 = -1e30f, mt1 = -1e30f;
#pragma unroll
        for (int q = 0; q < 8; q++) {
            int col = kt * 64 + q * 8 + 2 * (lane & 3);
            if (dmask) {
                sc[q][0] = (col     <= r0g) ? sc[q][0] * 0.125f : -1e30f;
                sc[q][1] = (col + 1 <= r0g) ? sc[q][1] * 0.125f : -1e30f;
                sc[q][2] = (col     <= r1g) ? sc[q][2] * 0.125f : -1e30f;
                sc[q][3] = (col + 1 <= r1g) ? sc[q][3] * 0.125f : -1e30f;
            } else {
                sc[q][0] *= 0.125f; sc[q][1] *= 0.125f;
                sc[q][2] *= 0.125f; sc[q][3] *= 0.125f;
            }
            mt0 = fmaxf(mt0, fmaxf(sc[q][0], sc[q][1]));
            mt1 = fmaxf(mt1, fmaxf(sc[q][2], sc[q][3]));
        }
        mt0 = fmaxf(mt0, __shfl_xor_sync(0xffffffffu, mt0, 1));
        mt0 = fmaxf(mt0, __shfl_xor_sync(0xffffffffu, mt0, 2));
        mt1 = fmaxf(mt1, __shfl_xor_sync(0xffffffffu, mt1, 1));
        mt1 = fmaxf(mt1, __shfl_xor_sync(0xffffffffu, mt1, 2));
        float mn0 = fmaxf(m0, mt0), mn1 = fmaxf(m1, mt1);
        float e0 = __expf(m0 - mn0), e1 = __expf(m1 - mn1);
        m0 = mn0; m1 = mn1;
        float ls0 = 0.f, ls1 = 0.f;
#pragma unroll
        for (int q = 0; q < 8; q++) {
            sc[q][0] = __expf(sc[q][0] - mn0); ls0 += sc[q][0];
            sc[q][1] = __expf(sc[q][1] - mn0); ls0 += sc[q][1];
            sc[q][2] = __expf(sc[q][2] - mn1); ls1 += sc[q][2];
            sc[q][3] = __expf(sc[q][3] - mn1); ls1 += sc[q][3];
        }
        ls0 += __shfl_xor_sync(0xffffffffu, ls0, 1);
        ls0 += __shfl_xor_sync(0xffffffffu, ls0, 2);
        ls1 += __shfl_xor_sync(0xffffffffu, ls1, 1);
        ls1 += __shfl_xor_sync(0xffffffffu, ls1, 2);
        l0s = l0s * e0 + ls0;
        l1s = l1s * e1 + ls1;
#pragma unroll
        for (int q = 0; q < 8; q++) {
            oc[q][0] *= e0; oc[q][1] *= e0;
            oc[q][2] *= e1; oc[q][3] *= e1;
        }

#pragma unroll
        for (int kk = 0; kk < 4; kk++) {
            bf16 ph[8], pl[8];
            split2(sc[2 * kk][0],     ph[0], pl[0]);
            split2(sc[2 * kk][1],     ph[1], pl[1]);
            split2(sc[2 * kk][2],     ph[2], pl[2]);
            split2(sc[2 * kk][3],     ph[3], pl[3]);
            split2(sc[2 * kk + 1][0], ph[4], pl[4]);
            split2(sc[2 * kk + 1][1], ph[5], pl[5]);
            split2(sc[2 * kk + 1][2], ph[6], pl[6]);
            split2(sc[2 * kk + 1][3], ph[7], pl[7]);
            uint4 Ah = make_uint4(pack2bf(ph[0], ph[1]), pack2bf(ph[2], ph[3]),
                                  pack2bf(ph[4], ph[5]), pack2bf(ph[6], ph[7]));
            uint4 Al = make_uint4(pack2bf(pl[0], pl[1]), pack2bf(pl[2], pl[3]),
                                  pack2bf(pl[4], pl[5]), pack2bf(pl[6], pl[7]));
            int kb = kk * 32 + (lane >> 4) * 16;
#pragma unroll
            for (int q = 0; q < 4; q++) {
                uint32_t boff = swz((q * 16 + (lane & 15)) * 128 + kb);
                uint4 Vh = ldsm4(sb + 49152 + boff);
                uint4 Vl = ldsm4(sb + 57344 + boff);
                mma16816(oc[2 * q],     Ah, Vh.x, Vh.z);
                mma16816(oc[2 * q + 1], Ah, Vh.y, Vh.w);
                mma16816(oc[2 * q],     Al, Vh.x, Vh.z);
                mma16816(oc[2 * q + 1], Al, Vh.y, Vh.w);
                mma16816(oc[2 * q],     Ah, Vl.x, Vl.z);
                mma16816(oc[2 * q + 1], Ah, Vl.y, Vl.w);
            }
        }
    }

    float inv0 = 1.0f / l0s, inv1 = 1.0f / l1s;
    int tok0 = b * TT + qb * 128 + warp_m + (lane >> 2);
#pragma unroll
    for (int q = 0; q < 8; q++) {
        int c = h * DHH + q * 8 + 2 * (lane & 3);
        bf16 h0, l0, h1, l1;
        split2(oc[q][0] * inv0, h0, l0);
        split2(oc[q][1] * inv0, h1, l1);
        *(uint32_t*)&aoH[(size_t)tok0 * DD + c] = pack2bf(h0, h1);
        *(uint32_t*)&aoL[(size_t)tok0 * DD + c] = pack2bf(l0, l1);
        split2(oc[q][2] * inv1, h0, l0);
        split2(oc[q][3] * inv1, h1, l1);
        *(uint32_t*)&aoH[(size_t)(tok0 + 8) * DD + c] = pack2bf(h0, h1);
        *(uint32_t*)&aoL[(size_t)(tok0 + 8) * DD + c] = pack2bf(l0, l1);
    }
}

// ---------------- Router ----------------
__launch_bounds__(256)
__global__ void router_kernel(const float* __restrict__ h2,
                              const float* __restrict__ noise,
                              const float* __restrict__ w_rl,
                              const float* __restrict__ b_rl,
                              const float* __restrict__ w_rn,
                              const float* __restrict__ b_rn)
{
    int n = blockIdx.x;
    int tid = threadIdx.x;
    int lane = tid & 31, wid = tid >> 5;
    const float* hr = h2 + (size_t)n * DD;

    float aL[8], aN[8];
#pragma unroll
    for (int e = 0; e < 8; e++) { aL[e] = 0.f; aN[e] = 0.f; }

    for (int d = tid; d < DD; d += 256) {
        float hv = hr[d];
        const float4* rl4 = (const float4*)(w_rl + (size_t)d * 8);
        const float4* rn4 = (const float4*)(w_rn + (size_t)d * 8);
        float4 l0 = rl4[0], l1 = rl4[1];
        float4 n0 = rn4[0], n1 = rn4[1];
        aL[0] += hv * l0.x; aL[1] += hv * l0.y; aL[2] += hv * l0.z; aL[3] += hv * l0.w;
        aL[4] += hv * l1.x; aL[5] += hv * l1.y; aL[6] += hv * l1.z; aL[7] += hv * l1.w;
        aN[0] += hv * n0.x; aN[1] += hv * n0.y; aN[2] += hv * n0.z; aN[3] += hv * n0.w;
        aN[4] += hv * n1.x; aN[5] += hv * n1.y; aN[6] += hv * n1.z; aN[7] += hv * n1.w;
    }
#pragma unroll
    for (int e = 0; e < 8; e++) { aL[e] = warpReduceSum(aL[e]); aN[e] = warpReduceSum(aN[e]); }

    __shared__ float sL[8][8], sN[8][8];
    if (lane == 0) {
#pragma unroll
        for (int e = 0; e < 8; e++) { sL[wid][e] = aL[e]; sN[wid][e] = aN[e]; }
    }
    __syncthreads();

    if (tid == 0) {
        float v0 = -1e38f, v1 = -1e38f;
        int i0 = 0, i1 = 0;
#pragma unroll
        for (int e = 0; e < 8; e++) {
            float L = 0.f, Nn = 0.f;
#pragma unroll
            for (int w = 0; w < 8; w++) { L += sL[w][e]; Nn += sN[w][e]; }
            float spin = Nn + b_rn[e];
            float sp = fmaxf(spin, 0.f) + log1pf(expf(-fabsf(spin)));
            float v = L + b_rl[e] + noise[(size_t)n * 8 + e] * sp;
            if (v > v0)      { v1 = v0; i1 = i0; v0 = v; i0 = e; }
            else if (v > v1) { v1 = v;  i1 = e; }
        }
        float ex = expf(v1 - v0);
        float inv = 1.0f / (1.0f + ex);
        g_tix[n * 2]     = i0;
        g_tix[n * 2 + 1] = i1;
        g_tgate[n * 2]     = inv;
        g_tgate[n * 2 + 1] = ex * inv;
    }
}

// ---------------- Expert assignment ----------------
__launch_bounds__(256)
__global__ void assign_kernel()
{
    int e = blockIdx.x;
    int tid = threadIdx.x;
    int lane = tid & 31, wid = tid >> 5;
    __shared__ int warpsum[8];

    int flags[8];
    int cnt = 0;
#pragma unroll
    for (int i = 0; i < 8; i++) {
        int tok = tid * 8 + i;
        int f = 0;
        if (g_tix[tok * 2] == e) f = 1;
        else if (g_tix[tok * 2 + 1] == e) f = 2;
        flags[i] = f;
        cnt += (f != 0);
    }
    int incl = cnt;
#pragma unroll
    for (int off = 1; off < 32; off <<= 1) {
        int v = __shfl_up_sync(0xffffffffu, incl, off);
        if (lane >= off) incl += v;
    }
    if (lane == 31) warpsum[wid] = incl;
    __syncthreads();
    int wbase = 0;
    for (int w = 0; w < wid; w++) wbase += warpsum[w];
    int base = wbase + incl - cnt;

#pragma unroll
    for (int i = 0; i < 8; i++) {
        if (flags[i]) {
            if (base < CAP) {
                int tok = tid * 8 + i;
                g_expert_tok[e * CAP + base]  = tok;
                g_expert_gate[e * CAP + base] = g_tgate[tok * 2 + (flags[i] - 1)];
            }
            base++;
        }
    }
}

// ---------------- weight transpose + split (128B-coalesced stores) ----------------
// W [e][K][N] fp32 -> Oh (and optionally Ol) [e][N][K] bf16
// Tile: 64 k-rows x 32 n-cols. Loads: 128B rows. Stores: one warp per n-row,
// 32 lanes x uint32 (2 k-elems) = 128B contiguous.
__global__ void conv_w_kernel(const float* __restrict__ W,
                              bf16* __restrict__ Oh, bf16* __restrict__ Ol,
                              int K, int N)
{
    __shared__ float tile[64][33];
    int e = blockIdx.z;
    const float* Wp = W + (size_t)e * K * N;
    size_t ob = (size_t)e * K * N;
    int n0 = blockIdx.x * 32, k0 = blockIdx.y * 64;
    int tx = threadIdx.x, ty = threadIdx.y;   // 32 x 8
#pragma unroll
    for (int i = 0; i < 64; i += 8)
        tile[ty + i][tx] = Wp[(size_t)(k0 + ty + i) * N + n0 + tx];
    __syncthreads();
    // warp ty handles n-rows {ty, ty+8, ty+16, ty+24}; lane tx covers k-pair 2*tx
#pragma unroll
    for (int it = 0; it < 4; it++) {
        int nl = ty + it * 8;
        float v0 = tile[2 * tx][nl];
        float v1 = tile[2 * tx + 1][nl];
        bf16 h0, l0, h1, l1;
        split2(v0, h0, l0);
        split2(v1, h1, l1);
        size_t o = ob + (size_t)(n0 + nl) * K + k0 + 2 * tx;
        *(uint32_t*)&Oh[o] = pack2bf(h0, h1);
        if (Ol) *(uint32_t*)&Ol[o] = pack2bf(l0, l1);
    }
}

// ---------------- split-bf16 tensor-core GEMM (proven structure) ----------------
// C[M][N] = A[M][K] @ B[N][K]^T.  K-chunk 64, double-buffered, 128B-row SW128.
// S3=1: 3-term split, stage 64KB (Ah|Al|Bh|Bl), occupancy 1.
// S3=0: 2-term split, stage compacted to 48KB (Ah|Al|Bh), occupancy 2.
// MODE 0: C = A@B                                (qkv)
// MODE 1: C = C2 = X + A@B                       (attn proj + residual)
// MODE 2: hc = relu(gather(A)@B + b1[e])         (expert up; A rows via g_expert_tok)
// MODE 3: out[tok] += (A@B + b2[e]) * gate       (expert down, atomic scatter)
#define GEMM_SMEM_S3  (2 * 65536)
#define GEMM_SMEM_S2  (2 * 49152)

template<bool S3>
__device__ __forceinline__ void compute_stage(uint32_t sb, int warp_m, int warp_n,
                                              int lane, float acc[2][8][4])
{
    int lr = lane & 15, lc = lane >> 4;
#pragma unroll
    for (int k16 = 0; k16 < 4; k16++) {
        int kb = k16 * 32 + lc * 16;
        uint32_t a0o = swz((warp_m + lr) * 128 + kb);
        uint32_t a1o = swz((warp_m + 16 + lr) * 128 + kb);
        uint4 Ah0 = ldsm4(sb + a0o);
        uint4 Ah1 = ldsm4(sb + a1o);
        uint4 Al0 = ldsm4(sb + 16384 + a0o);
        uint4 Al1 = ldsm4(sb + 16384 + a1o);
#pragma unroll
        for (int q = 0; q < 4; q++) {
            uint32_t off = swz((warp_n + q * 16 + lr) * 128 + kb);
            uint4 Bh = ldsm4(sb + 32768 + off);
            mma16816(acc[0][q * 2 + 0], Ah0, Bh.x, Bh.z);
            mma16816(acc[0][q * 2 + 1], Ah0, Bh.y, Bh.w);
            mma16816(acc[1][q * 2 + 0], Ah1, Bh.x, Bh.z);
            mma16816(acc[1][q * 2 + 1], Ah1, Bh.y, Bh.w);
            mma16816(acc[0][q * 2 + 0], Al0, Bh.x, Bh.z);
            mma16816(acc[0][q * 2 + 1], Al0, Bh.y, Bh.w);
            mma16816(acc[1][q * 2 + 0], Al1, Bh.x, Bh.z);
            mma16816(acc[1][q * 2 + 1], Al1, Bh.y, Bh.w);
            if (S3) {
                uint4 Bl = ldsm4(sb + 49152 + off);
                mma16816(acc[0][q * 2 + 0], Ah0, Bl.x, Bl.z);
                mma16816(acc[0][q * 2 + 1], Ah0, Bl.y, Bl.w);
                mma16816(acc[1][q * 2 + 0], Ah1, Bl.x, Bl.z);
                mma16816(acc[1][q * 2 + 1], Ah1, Bl.y, Bl.w);
            }
        }
    }
}

template<int MODE, bool S3>
__launch_bounds__(256, S3 ? 1 : 2)
__global__ void gemm_bf16(const bf16* __restrict__ Ah, const bf16* __restrict__ Al,
                          const bf16* __restrict__ Bh, const bf16* __restrict__ Bl,
                          float* __restrict__ C, float* __restrict__ C2,
                          const float* __restrict__ Xres,
                          const float* __restrict__ bias,
                          bf16* __restrict__ Oh, bf16* __restrict__ Ol,
                          int K, int N)
{
    constexpr uint32_t STAGE = S3 ? 65536u : 49152u;
    extern __shared__ __align__(128) char dsm[];
    const uint32_t sb0 = smem_u32(dsm);
    const int tid = threadIdx.x, lane = tid & 31, wid = tid >> 5;
    const int e = blockIdx.z;
    const int m0 = blockIdx.y * 128, n0 = blockIdx.x * 128;
    const int warp_m = (wid >> 1) * 32, warp_n = (wid & 1) * 64;

    const size_t rK = (size_t)K * 2;   // bytes per row
    const char* pAh;
    const char* pAl;
    if (MODE == 2) { pAh = (const char*)Ah; pAl = (const char*)Al; }  // token-indirect rows
    else if (MODE == 3) {
        pAh = (const char*)(Ah + ((size_t)e * CAP + m0) * K);
        pAl = (const char*)(Al + ((size_t)e * CAP + m0) * K);
    } else {
        pAh = (const char*)(Ah + (size_t)m0 * K);
        pAl = (const char*)(Al + (size_t)m0 * K);
    }
    const char* pBh = (const char*)(Bh + ((MODE >= 2) ? (size_t)e * N * K : 0) + (size_t)n0 * K);
    const char* pBl = (const char*)(S3 ? (Bl + ((MODE >= 2) ? (size_t)e * N * K : 0) + (size_t)n0 * K) : nullptr);
    const int NC = K >> 6;

    auto issue = [&](int c) {
        uint32_t sbuf = sb0 + (c & 1) * STAGE;
        int kb = c * 128;
#pragma unroll
        for (int i = 0; i < 4; i++) {
            int idx = tid + i * 256;
            int row = idx >> 3;
            int c16 = (idx & 7) * 16;
            uint32_t sw = swz(row * 128 + c16);
            size_t goA;
            if (MODE == 2) {
                int tok = g_expert_tok[e * CAP + m0 + row];
                goA = (size_t)tok * rK + kb + c16;
            } else {
                goA = (size_t)row * rK + kb + c16;
            }
            size_t goB = (size_t)row * rK + kb + c16;
            cpa16(sbuf + sw,         pAh + goA);
            cpa16(sbuf + 16384 + sw, pAl + goA);
            cpa16(sbuf + 32768 + sw, pBh + goB);
            if (S3) cpa16(sbuf + 49152 + sw, pBl + goB);
        }
        asm volatile("cp.async.commit_group;" ::: "memory");
    };

    float acc[2][8][4];
#pragma unroll
    for (int a = 0; a < 2; a++)
#pragma unroll
        for (int b = 0; b < 8; b++)
#pragma unroll
            for (int c = 0; c < 4; c++) acc[a][b][c] = 0.f;

    issue(0);
    for (int c = 0; c < NC; c++) {
        if (c + 1 < NC) {
            issue(c + 1);
            asm volatile("cp.async.wait_group 1;" ::: "memory");
        } else {
            asm volatile("cp.async.wait_group 0;" ::: "memory");
        }
        __syncthreads();
        compute_stage<S3>(sb0 + (c & 1) * STAGE, warp_m, warp_n, lane, acc);
        __syncthreads();
    }

    // epilogue
#pragma unroll
    for (int mt = 0; mt < 2; mt++) {
#pragma unroll
        for (int rh = 0; rh < 2; rh++) {
            int gr = m0 + warp_m + mt * 16 + rh * 8 + (lane >> 2);
            int tok = 0; float gt = 0.f;
            if (MODE == 3) {
                int slot = e * CAP + gr;
                tok = g_expert_tok[slot];
                gt = g_expert_gate[slot];
            }
#pragma unroll
            for (int nt = 0; nt < 8; nt++) {
                int gc = n0 + warp_n + nt * 8 + (lane & 3) * 2;
                float d0 = acc[mt][nt][rh * 2 + 0];
                float d1 = acc[mt][nt][rh * 2 + 1];
                if (MODE == 0) {
                    *(float2*)&C[(size_t)gr * N + gc] = make_float2(d0, d1);
                } else if (MODE == 1) {
                    size_t ix = (size_t)gr * N + gc;
                    float2 xv = *(const float2*)&Xres[ix];
                    float2 v = make_float2(d0 + xv.x, d1 + xv.y);
                    *(float2*)&C[ix] = v;
                    *(float2*)&C2[ix] = v;
                } else if (MODE == 2) {
                    float v0 = fmaxf(d0 + bias[(size_t)e * N + gc], 0.f);
                    float v1 = fmaxf(d1 + bias[(size_t)e * N + gc + 1], 0.f);
                    bf16 h0, l0, h1, l1;
                    split2(v0, h0, l0);
                    split2(v1, h1, l1);
                    size_t ix = ((size_t)e * CAP + gr) * (size_t)N + gc;
                    *(uint32_t*)&Oh[ix] = pack2bf(h0, h1);
                    *(uint32_t*)&Ol[ix] = pack2bf(l0, l1);
                } else {
                    if (gt != 0.f) {
                        float v0 = (d0 + bias[(size_t)e * N + gc]) * gt;
                        float v1 = (d1 + bias[(size_t)e * N + gc + 1]) * gt;
                        atomicAdd(&C2[(size_t)tok * DD + gc], v0);
                        atomicAdd(&C2[(size_t)tok * DD + gc + 1], v1);
                    }
                }
            }
        }
    }
}

// ---------------- launch ----------------
extern "C" void kernel_launch(void* const* d_in, const int* in_sizes, int n_in,
                              void* d_out, int out_size)
{
    const float* x      = (const float*)d_in[0];
    const float* noise  = (const float*)d_in[1];
    const float* ln1_g  = (const float*)d_in[2];
    const float* ln1_b  = (const float*)d_in[3];
    const float* ln2_g  = (const float*)d_in[4];
    const float* ln2_b  = (const float*)d_in[5];
    const float* w_qkv  = (const float*)d_in[6];
    const float* w_proj = (const float*)d_in[7];
    const float* w_rl   = (const float*)d_in[8];
    const float* b_rl   = (const float*)d_in[9];
    const float* w_rn   = (const float*)d_in[10];
    const float* b_rn   = (const float*)d_in[11];
    const float* w1     = (const float*)d_in[12];
    const float* b1     = (const float*)d_in[13];
    const float* w2     = (const float*)d_in[14];
    const float* b2     = (const float*)d_in[15];
    float* out = (float*)d_out;

    float *p_qkv, *p_x2, *p_h2;
    bf16 *p_hH, *p_hL, *p_aoH, *p_aoL, *p_h2H, *p_h2L;
    bf16 *p_wqkvTh, *p_wqkvTl, *p_wprojTh, *p_wprojTl;
    bf16 *p_w1th, *p_w2th;
    bf16 *p_hcH, *p_hcL;
    cudaGetSymbolAddress((void**)&p_qkv, g_qkv);
    cudaGetSymbolAddress((void**)&p_x2,  g_x2);
    cudaGetSymbolAddress((void**)&p_h2,  g_h2);
    cudaGetSymbolAddress((void**)&p_hH,  g_hHi);
    cudaGetSymbolAddress((void**)&p_hL,  g_hLo);
    cudaGetSymbolAddress((void**)&p_aoH, g_aoHi);
    cudaGetSymbolAddress((void**)&p_aoL, g_aoLo);
    cudaGetSymbolAddress((void**)&p_h2H, g_h2Hi);
    cudaGetSymbolAddress((void**)&p_h2L, g_h2Lo);
    cudaGetSymbolAddress((void**)&p_wqkvTh, g_wqkvTh);
    cudaGetSymbolAddress((void**)&p_wqkvTl, g_wqkvTl);
    cudaGetSymbolAddress((void**)&p_wprojTh, g_wprojTh);
    cudaGetSymbolAddress((void**)&p_wprojTl, g_wprojTl);
    cudaGetSymbolAddress((void**)&p_w1th, g_w1th);
    cudaGetSymbolAddress((void**)&p_w2th, g_w2th);
    cudaGetSymbolAddress((void**)&p_hcH, g_hcHi);
    cudaGetSymbolAddress((void**)&p_hcL, g_hcLo);

    cudaFuncSetAttribute((const void*)gemm_bf16<0, true>,  cudaFuncAttributeMaxDynamicSharedMemorySize, GEMM_SMEM_S3);
    cudaFuncSetAttribute((const void*)gemm_bf16<1, true>,  cudaFuncAttributeMaxDynamicSharedMemorySize, GEMM_SMEM_S3);
    cudaFuncSetAttribute((const void*)gemm_bf16<2, false>, cudaFuncAttributeMaxDynamicSharedMemorySize, GEMM_SMEM_S2);
    cudaFuncSetAttribute((const void*)gemm_bf16<3, false>, cudaFuncAttributeMaxDynamicSharedMemorySize, GEMM_SMEM_S2);
    cudaFuncSetAttribute(attn_mma_kernel, cudaFuncAttributeMaxDynamicSharedMemorySize, ATT_SMEM);

    // weight transpose + split (MoE weights: hi only — 2-term GEMMs)
    conv_w_kernel<<<dim3(3 * DD / 32, DD / 64, 1), dim3(32, 8)>>>(w_qkv, p_wqkvTh, p_wqkvTl, DD, 3 * DD);
    conv_w_kernel<<<dim3(DD / 32, DD / 64, 1), dim3(32, 8)>>>(w_proj, p_wprojTh, p_wprojTl, DD, DD);
    conv_w_kernel<<<dim3(DFF / 32, DD / 64, NEXP), dim3(32, 8)>>>(w1, p_w1th, nullptr, DD, DFF);
    conv_w_kernel<<<dim3(DD / 32, DFF / 64, NEXP), dim3(32, 8)>>>(w2, p_w2th, nullptr, DFF, DD);

    // 1. h = LN1(x)  (split only)
    ln_kernel<<<NTOK, 256>>>(x, ln1_g, ln1_b, nullptr, p_hH, p_hL);
    // 2. qkv = h @ w_qkv   [tensor, 3-term, occ1]
    gemm_bf16<0, true><<<dim3(24, 16, 1), 256, GEMM_SMEM_S3>>>(p_hH, p_hL, p_wqkvTh, p_wqkvTl,
                                                               p_qkv, nullptr, nullptr, nullptr,
                                                               nullptr, nullptr, DD, 3 * DD);
    // 3. RoPE
    rope_kernel<<<NTOK, 256>>>(p_qkv);
    // 4. attention [tensor, 3-term]  (128-query tiles -> grid.x = TT/128 = 8)
    attn_mma_kernel<<<dim3(8, HH, BB), 256, ATT_SMEM>>>(p_qkv, p_aoH, p_aoL);
    // 5. x2 = x + ao @ w_proj  (seeds out)   [tensor, 3-term, occ1]
    gemm_bf16<1, true><<<dim3(8, 16, 1), 256, GEMM_SMEM_S3>>>(p_aoH, p_aoL, p_wprojTh, p_wprojTl,
                                                              p_x2, out, x, nullptr,
                                                              nullptr, nullptr, DD, DD);
    // 6. h2 = LN2(x2)  (fp32 + split)
    ln_kernel<<<NTOK, 256>>>(p_x2, ln2_g, ln2_b, p_h2, p_h2H, p_h2L);
    // 7. router
    router_kernel<<<NTOK, 256>>>(p_h2, noise, w_rl, b_rl, w_rn, b_rn);
    // 8. capacity assignment
    assign_kernel<<<NEXP, 256>>>();
    // 9. expert up (gather fused): hc = relu(h2[tok] @ w1 + b1)   [tensor, 2-term, occ2]
    gemm_bf16<2, false><<<dim3(DFF / 128, CAP / 128, NEXP), 256, GEMM_SMEM_S2>>>(
        p_h2H, p_h2L, p_w1th, nullptr, nullptr, nullptr, nullptr, b1, p_hcH, p_hcL, DD, DFF);
    // 10. expert down: out += (hc @ w2 + b2) * gate   [tensor, 2-term, occ2]
    gemm_bf16<3, false><<<dim3(DD / 128, CAP / 128, NEXP), 256, GEMM_SMEM_S2>>>(
        p_hcH, p_hcL, p_w2th, nullptr, nullptr, out, nullptr, b2, nullptr, nullptr, DFF, DD);
}